// round 10
// baseline (speedup 1.0000x reference)
#include <cuda_runtime.h>
#include <cuda_bf16.h>
#include <mma.h>
#include <cstdint>

using namespace nvcuda;

#define B_ROWS 32768
#define FDIM   512
#define NCOLS  1024
#define NCLS   1000

#define BM 128
#define BN 64
#define BK 32
#define LDA 40               // bf16 smem pitch (80B)
#define LDE 68               // fp32 epilogue pitch (272B, 16B-aligned)
#define NIT 16               // 512/32
#define TILE_A 10240         // 128x32 bf16 @ 80B pitch
#define TILE_W 5120          // 64x32 bf16 @ 80B pitch
#define STAGE_BYTES 30720    // Ahi+Alo+Whi+Wlo
#define SMEM_GEMM (2 * STAGE_BYTES)   // 61440 (>= 128*68*4 = 34816 epilogue)

// scatter: 4-row tile -> 6 CTAs/SM
#define SROWS 4
#define SC_WSM 0                        // [4][1024] f = 16384B
#define SC_OFF 16384                    // int[1001]
#define SC_SRC 20488                    // int[1024]
#define SMEM_SCAT 24584

__device__ int   g_cls_off[NCLS + 1];
__device__ int   g_cls_src[NCOLS];
__device__ __nv_bfloat16 g_Ahi[(size_t)B_ROWS * FDIM];
__device__ __nv_bfloat16 g_Alo[(size_t)B_ROWS * FDIM];
__device__ __nv_bfloat16 g_Whi[NCOLS * FDIM];
__device__ __nv_bfloat16 g_Wlo[NCOLS * FDIM];
__device__ float g_scratch[(size_t)B_ROWS * NCOLS];

__device__ __forceinline__ uint32_t smem_u32(const void* p) {
    uint32_t a;
    asm("{ .reg .u64 t; cvta.to.shared.u64 t, %1; cvt.u32.u64 %0, t; }" : "=r"(a) : "l"(p));
    return a;
}
__device__ __forceinline__ void cp16(uint32_t dst, const void* src) {
    asm volatile("cp.async.cg.shared.global [%0], [%1], 16;" :: "r"(dst), "l"(src) : "memory");
}

// ---- prep: deterministic CSR of label_ids ----
__global__ void prep_kernel(const int* __restrict__ label_ids) {
    __shared__ int lab[NCOLS];
    __shared__ int cnt[NCLS];
    __shared__ int off[NCLS + 1];
    int t = threadIdx.x;
    lab[t] = label_ids[t];
    __syncthreads();
    if (t < NCLS) {
        int c = 0;
        for (int i = 0; i < NCOLS; i++) c += (lab[i] == t);
        cnt[t] = c;
    }
    __syncthreads();
    if (t == 0) {
        int acc = 0;
        for (int c = 0; c < NCLS; c++) { off[c] = acc; acc += cnt[c]; }
        off[NCLS] = acc;
    }
    __syncthreads();
    if (t <= NCLS) g_cls_off[t] = off[t];
    if (t < NCLS) {
        int pos = off[t];
        for (int i = 0; i < NCOLS; i++)
            if (lab[i] == t) g_cls_src[pos++] = i;
    }
}

// ---- prep: fp32 -> bf16 hi/lo for A and W in one launch ----
#define A_BLOCKS ((B_ROWS * FDIM) / 1024)
__global__ void prep_split(const float* __restrict__ A, const float* __restrict__ W,
                           __nv_bfloat16* __restrict__ Ahi, __nv_bfloat16* __restrict__ Alo,
                           __nv_bfloat16* __restrict__ Whi, __nv_bfloat16* __restrict__ Wlo) {
    int blk = blockIdx.x;
    const float* src;
    __nv_bfloat16 *hi, *lo;
    size_t i0;
    if (blk < A_BLOCKS) {
        src = A; hi = Ahi; lo = Alo;
        i0 = ((size_t)blk * 256 + threadIdx.x) * 4;
    } else {
        src = W; hi = Whi; lo = Wlo;
        i0 = ((size_t)(blk - A_BLOCKS) * 256 + threadIdx.x) * 4;
    }
    float4 v = *(const float4*)(src + i0);
    __nv_bfloat16 h[4], l[4];
    float x;
    x = v.x; h[0] = __float2bfloat16_rn(x); l[0] = __float2bfloat16_rn(x - __bfloat162float(h[0]));
    x = v.y; h[1] = __float2bfloat16_rn(x); l[1] = __float2bfloat16_rn(x - __bfloat162float(h[1]));
    x = v.z; h[2] = __float2bfloat16_rn(x); l[2] = __float2bfloat16_rn(x - __bfloat162float(h[2]));
    x = v.w; h[3] = __float2bfloat16_rn(x); l[3] = __float2bfloat16_rn(x - __bfloat162float(h[3]));
    *(uint2*)(hi + i0) = *(uint2*)h;
    *(uint2*)(lo + i0) = *(uint2*)l;
}

// ---- GEMM: 128x64 tile, 3 CTAs/SM, fused 3-product split, double-buffered ----
__global__ void __launch_bounds__(256, 3)
mhc_gemm(const float* __restrict__ gprob, const float* __restrict__ bias) {
    extern __shared__ char smem[];
    const uint32_t sb = smem_u32(smem);
    const int t   = threadIdx.x;
    const int wid = t >> 5;
    const int n0   = blockIdx.x * BN;    // group id == blockIdx.x
    const int row0 = blockIdx.y * BM;
    const int wm0 = (wid & 3) * 32;      // warp tile 32x32
    const int wn0 = (wid >> 2) * 32;

    wmma::fragment<wmma::accumulator, 16, 16, 16, float> acc[2][2];
#pragma unroll
    for (int fm = 0; fm < 2; fm++)
#pragma unroll
        for (int fn = 0; fn < 2; fn++) wmma::fill_fragment(acc[fm][fn], 0.0f);

    auto issue = [&](int it, int s) {
        if (it < NIT) {
            const char* ah = (const char*)(g_Ahi + (size_t)row0 * FDIM + it * BK);
            const char* al = (const char*)(g_Alo + (size_t)row0 * FDIM + it * BK);
            const char* wh = (const char*)(g_Whi + (size_t)n0 * FDIM + it * BK);
            const char* wl = (const char*)(g_Wlo + (size_t)n0 * FDIM + it * BK);
            uint32_t st = sb + s * STAGE_BYTES;
#pragma unroll
            for (int i = 0; i < 2; i++) {          // A: 512 chunks, 2/thread
                int id = i * 256 + t;
                int r = id >> 2, co = (id & 3) * 16;
                size_t go = (size_t)r * 1024 + co;
                uint32_t so = r * 80 + co;
                cp16(st + so,          ah + go);
                cp16(st + TILE_A + so, al + go);
            }
            {                                       // W: 256 chunks, 1/thread
                int r = t >> 2, co = (t & 3) * 16;
                size_t go = (size_t)r * 1024 + co;
                uint32_t so = r * 80 + co;
                cp16(st + 2 * TILE_A + so,          wh + go);
                cp16(st + 2 * TILE_A + TILE_W + so, wl + go);
            }
        }
        asm volatile("cp.async.commit_group;" ::: "memory");
    };

    issue(0, 0);
    for (int it = 0; it < NIT; ++it) {
        int s = it & 1;
        issue(it + 1, s ^ 1);
        asm volatile("cp.async.wait_group 1;" ::: "memory");
        __syncthreads();

        const __nv_bfloat16* ah_sm = (const __nv_bfloat16*)(smem + s * STAGE_BYTES);
        const __nv_bfloat16* al_sm = (const __nv_bfloat16*)(smem + s * STAGE_BYTES + TILE_A);
        const __nv_bfloat16* wh_sm = (const __nv_bfloat16*)(smem + s * STAGE_BYTES + 2 * TILE_A);
        const __nv_bfloat16* wl_sm = (const __nv_bfloat16*)(smem + s * STAGE_BYTES + 2 * TILE_A + TILE_W);
#pragma unroll
        for (int kk = 0; kk < BK; kk += 16) {
            wmma::fragment<wmma::matrix_a, 16, 16, 16, __nv_bfloat16, wmma::row_major> afh[2], afl[2];
            wmma::fragment<wmma::matrix_b, 16, 16, 16, __nv_bfloat16, wmma::col_major> bfh[2], bfl[2];
#pragma unroll
            for (int fm = 0; fm < 2; fm++)
                wmma::load_matrix_sync(afh[fm], ah_sm + (wm0 + fm * 16) * LDA + kk, LDA);
#pragma unroll
            for (int fn = 0; fn < 2; fn++)
                wmma::load_matrix_sync(bfh[fn], wh_sm + (wn0 + fn * 16) * LDA + kk, LDA);
#pragma unroll
            for (int fm = 0; fm < 2; fm++)
#pragma unroll
                for (int fn = 0; fn < 2; fn++)
                    wmma::mma_sync(acc[fm][fn], afh[fm], bfh[fn], acc[fm][fn]);
#pragma unroll
            for (int fm = 0; fm < 2; fm++)
                wmma::load_matrix_sync(afl[fm], al_sm + (wm0 + fm * 16) * LDA + kk, LDA);
#pragma unroll
            for (int fm = 0; fm < 2; fm++)
#pragma unroll
                for (int fn = 0; fn < 2; fn++)
                    wmma::mma_sync(acc[fm][fn], afl[fm], bfh[fn], acc[fm][fn]);
#pragma unroll
            for (int fn = 0; fn < 2; fn++)
                wmma::load_matrix_sync(bfl[fn], wl_sm + (wn0 + fn * 16) * LDA + kk, LDA);
#pragma unroll
            for (int fm = 0; fm < 2; fm++)
#pragma unroll
                for (int fn = 0; fn < 2; fn++)
                    wmma::mma_sync(acc[fm][fn], afh[fm], bfl[fn], acc[fm][fn]);
        }
        __syncthreads();
    }

    // ---- epilogue: frags -> smem -> (bias+gprob) -> scratch (coalesced f4) ----
    float* epi = (float*)smem;
#pragma unroll
    for (int fm = 0; fm < 2; fm++)
#pragma unroll
        for (int fn = 0; fn < 2; fn++)
            wmma::store_matrix_sync(epi + (wm0 + fm * 16) * LDE + wn0 + fn * 16,
                                    acc[fm][fn], LDE, wmma::mem_row_major);
    __syncthreads();

#pragma unroll
    for (int i = 0; i < 8; i++) {
        int idx = i * 256 + t;               // 2048 float4s in the 128x64 tile
        int r  = idx >> 4;
        int c4 = (idx & 15) * 4;
        float4 v = *(float4*)(epi + r * LDE + c4);
        int n = n0 + c4;
        float gp = __ldg(gprob + (size_t)(row0 + r) * 16 + blockIdx.x);  // one group per CTA
        v.x = (v.x + __ldg(bias + n + 0)) * gp;
        v.y = (v.y + __ldg(bias + n + 1)) * gp;
        v.z = (v.z + __ldg(bias + n + 2)) * gp;
        v.w = (v.w + __ldg(bias + n + 3)) * gp;
        *(float4*)(g_scratch + (size_t)(row0 + r) * NCOLS + n) = v;
    }
}

// ---- scatter: 4-row tiles, 6 CTAs/SM, class-outer/row-inner gather ----
__global__ void __launch_bounds__(256, 6)
mhc_scatter(float* __restrict__ out) {
    extern __shared__ char smem[];
    float* wsm    = (float*)(smem + SC_WSM);
    int*   off_sm = (int*)(smem + SC_OFF);
    int*   src_sm = (int*)(smem + SC_SRC);
    const int t = threadIdx.x;
    const int r0 = blockIdx.x * SROWS;

    for (int i = t; i <= NCLS; i += 256) off_sm[i] = g_cls_off[i];
    for (int i = t; i < NCOLS; i += 256) src_sm[i] = g_cls_src[i];

    const float4* src = (const float4*)(g_scratch + (size_t)r0 * NCOLS);
    float4* dst4 = (float4*)wsm;
#pragma unroll
    for (int i = 0; i < SROWS * NCOLS / 4 / 256; i++)
        dst4[i * 256 + t] = src[i * 256 + t];
    __syncthreads();

    for (int c = t; c < NCLS; c += 256) {
        int s0 = off_sm[c], s1 = off_sm[c + 1];
        float* ocol = out + (size_t)r0 * NCLS + c;
        if (s1 == s0) {
#pragma unroll
            for (int r = 0; r < SROWS; r++) ocol[(size_t)r * NCLS] = 0.f;
        } else if (s1 == s0 + 1) {
            int src0 = src_sm[s0];
#pragma unroll
            for (int r = 0; r < SROWS; r++)
                ocol[(size_t)r * NCLS] = wsm[r * NCOLS + src0];
        } else {
#pragma unroll
            for (int r = 0; r < SROWS; r++) {
                float s = 0.f;
                for (int k = s0; k < s1; k++) s += wsm[r * NCOLS + src_sm[k]];
                ocol[(size_t)r * NCLS] = s;
            }
        }
    }
}

extern "C" void kernel_launch(void* const* d_in, const int* in_sizes, int n_in,
                              void* d_out, int out_size) {
    const float* features = (const float*)d_in[0];
    const float* gprob    = (const float*)d_in[1];
    const float* W        = (const float*)d_in[2];
    const float* bias     = (const float*)d_in[3];
    const int*   labels   = (const int*)d_in[4];
    float* out = (float*)d_out;

    static __nv_bfloat16 *hA, *lA, *hW, *lW;
    static bool init = false;
    if (!init) {
        cudaGetSymbolAddress((void**)&hA, g_Ahi);
        cudaGetSymbolAddress((void**)&lA, g_Alo);
        cudaGetSymbolAddress((void**)&hW, g_Whi);
        cudaGetSymbolAddress((void**)&lW, g_Wlo);
        cudaFuncSetAttribute(mhc_gemm, cudaFuncAttributeMaxDynamicSharedMemorySize, SMEM_GEMM);
        cudaFuncSetAttribute(mhc_scatter, cudaFuncAttributeMaxDynamicSharedMemorySize, SMEM_SCAT);
        init = true;
    }

    prep_kernel<<<1, 1024>>>(labels);
    prep_split<<<A_BLOCKS + (NCOLS * FDIM) / 1024, 256>>>(features, W, hA, lA, hW, lW);

    dim3 grid(NCOLS / BN, B_ROWS / BM);
    mhc_gemm<<<grid, 256, SMEM_GEMM>>>(gprob, bias);
    mhc_scatter<<<B_ROWS / SROWS, 256, SMEM_SCAT>>>(out);
}

// round 11
// speedup vs baseline: 1.0754x; 1.0754x over previous
#include <cuda_runtime.h>
#include <cuda_bf16.h>
#include <mma.h>
#include <cstdint>

using namespace nvcuda;

#define B_ROWS 32768
#define FDIM   512
#define NCOLS  1024
#define NCLS   1000

#define BM 128
#define BN 128
#define BK 32
#define LDA 40               // bf16 smem pitch (80B)
#define LDE 136              // fp32 epilogue pitch
#define NIT 16               // 512/32 (all 3 products per chunk)
#define TILE_B 10240         // one 128x32 bf16 tile @ pitch 80
#define STAGE_BYTES 40960    // Ahi+Alo+Whi+Wlo
#define SMEM_GEMM (2 * STAGE_BYTES)   // 81920 (>= 128*136*4 = 69632 epilogue)

// scatter: 4-row tile -> 6 CTAs/SM (measured best)
#define SROWS 4
#define SC_WSM 0                        // [4][1024] f = 16384B
#define SC_OFF 16384                    // int[1001]
#define SC_SRC 20488                    // int[1024]
#define SMEM_SCAT 24584

__device__ int   g_cls_off[NCLS + 1];
__device__ int   g_cls_src[NCOLS];
__device__ __nv_bfloat16 g_Ahi[(size_t)B_ROWS * FDIM];
__device__ __nv_bfloat16 g_Alo[(size_t)B_ROWS * FDIM];
__device__ __nv_bfloat16 g_Whi[NCOLS * FDIM];
__device__ __nv_bfloat16 g_Wlo[NCOLS * FDIM];
__device__ float g_scratch[(size_t)B_ROWS * NCOLS];

__device__ __forceinline__ uint32_t smem_u32(const void* p) {
    uint32_t a;
    asm("{ .reg .u64 t; cvta.to.shared.u64 t, %1; cvt.u32.u64 %0, t; }" : "=r"(a) : "l"(p));
    return a;
}
__device__ __forceinline__ void cp16(uint32_t dst, const void* src) {
    asm volatile("cp.async.cg.shared.global [%0], [%1], 16;" :: "r"(dst), "l"(src) : "memory");
}

// ---- prep: deterministic CSR of label_ids ----
__global__ void prep_kernel(const int* __restrict__ label_ids) {
    __shared__ int lab[NCOLS];
    __shared__ int cnt[NCLS];
    __shared__ int off[NCLS + 1];
    int t = threadIdx.x;
    lab[t] = label_ids[t];
    __syncthreads();
    if (t < NCLS) {
        int c = 0;
        for (int i = 0; i < NCOLS; i++) c += (lab[i] == t);
        cnt[t] = c;
    }
    __syncthreads();
    if (t == 0) {
        int acc = 0;
        for (int c = 0; c < NCLS; c++) { off[c] = acc; acc += cnt[c]; }
        off[NCLS] = acc;
    }
    __syncthreads();
    if (t <= NCLS) g_cls_off[t] = off[t];
    if (t < NCLS) {
        int pos = off[t];
        for (int i = 0; i < NCOLS; i++)
            if (lab[i] == t) g_cls_src[pos++] = i;
    }
}

// ---- prep: fp32 -> bf16 hi/lo for A and W in one launch ----
#define A_BLOCKS ((B_ROWS * FDIM) / 1024)
__global__ void prep_split(const float* __restrict__ A, const float* __restrict__ W,
                           __nv_bfloat16* __restrict__ Ahi, __nv_bfloat16* __restrict__ Alo,
                           __nv_bfloat16* __restrict__ Whi, __nv_bfloat16* __restrict__ Wlo) {
    int blk = blockIdx.x;
    const float* src;
    __nv_bfloat16 *hi, *lo;
    size_t i0;
    if (blk < A_BLOCKS) {
        src = A; hi = Ahi; lo = Alo;
        i0 = ((size_t)blk * 256 + threadIdx.x) * 4;
    } else {
        src = W; hi = Whi; lo = Wlo;
        i0 = ((size_t)(blk - A_BLOCKS) * 256 + threadIdx.x) * 4;
    }
    float4 v = *(const float4*)(src + i0);
    __nv_bfloat16 h[4], l[4];
    float x;
    x = v.x; h[0] = __float2bfloat16_rn(x); l[0] = __float2bfloat16_rn(x - __bfloat162float(h[0]));
    x = v.y; h[1] = __float2bfloat16_rn(x); l[1] = __float2bfloat16_rn(x - __bfloat162float(h[1]));
    x = v.z; h[2] = __float2bfloat16_rn(x); l[2] = __float2bfloat16_rn(x - __bfloat162float(h[2]));
    x = v.w; h[3] = __float2bfloat16_rn(x); l[3] = __float2bfloat16_rn(x - __bfloat162float(h[3]));
    *(uint2*)(hi + i0) = *(uint2*)h;
    *(uint2*)(lo + i0) = *(uint2*)l;
}

// ---- GEMM: 128x128, fused 3-product split, double-buffered cp.async (R9 proven) ----
__global__ void __launch_bounds__(256, 2)
mhc_gemm(const float* __restrict__ gprob, const float* __restrict__ bias) {
    extern __shared__ char smem[];
    const uint32_t sb = smem_u32(smem);
    const int t   = threadIdx.x;
    const int wid = t >> 5;
    const int n0   = blockIdx.x * BN;
    const int row0 = blockIdx.y * BM;
    const int wm0 = (wid & 3) * 32;
    const int wn0 = (wid >> 2) * 64;

    wmma::fragment<wmma::accumulator, 16, 16, 16, float> acc[2][4];
#pragma unroll
    for (int fm = 0; fm < 2; fm++)
#pragma unroll
        for (int fn = 0; fn < 4; fn++) wmma::fill_fragment(acc[fm][fn], 0.0f);

    auto issue = [&](int it, int s) {
        if (it < NIT) {
            const char* ah = (const char*)(g_Ahi + (size_t)row0 * FDIM + it * BK);
            const char* al = (const char*)(g_Alo + (size_t)row0 * FDIM + it * BK);
            const char* wh = (const char*)(g_Whi + (size_t)n0 * FDIM + it * BK);
            const char* wl = (const char*)(g_Wlo + (size_t)n0 * FDIM + it * BK);
            uint32_t st = sb + s * STAGE_BYTES;
#pragma unroll
            for (int i = 0; i < 2; i++) {
                int id = i * 256 + t;
                int r = id >> 2, co = (id & 3) * 16;
                size_t go = (size_t)r * 1024 + co;
                uint32_t so = r * 80 + co;
                cp16(st + so,              ah + go);
                cp16(st + TILE_B + so,     al + go);
                cp16(st + 2 * TILE_B + so, wh + go);
                cp16(st + 3 * TILE_B + so, wl + go);
            }
        }
        asm volatile("cp.async.commit_group;" ::: "memory");
    };

    issue(0, 0);
    for (int it = 0; it < NIT; ++it) {
        int s = it & 1;
        issue(it + 1, s ^ 1);
        asm volatile("cp.async.wait_group 1;" ::: "memory");
        __syncthreads();

        const __nv_bfloat16* ah_sm = (const __nv_bfloat16*)(smem + s * STAGE_BYTES);
        const __nv_bfloat16* al_sm = (const __nv_bfloat16*)(smem + s * STAGE_BYTES + TILE_B);
        const __nv_bfloat16* wh_sm = (const __nv_bfloat16*)(smem + s * STAGE_BYTES + 2 * TILE_B);
        const __nv_bfloat16* wl_sm = (const __nv_bfloat16*)(smem + s * STAGE_BYTES + 3 * TILE_B);
#pragma unroll
        for (int kk = 0; kk < BK; kk += 16) {
            wmma::fragment<wmma::matrix_a, 16, 16, 16, __nv_bfloat16, wmma::row_major> afh[2], afl[2];
            wmma::fragment<wmma::matrix_b, 16, 16, 16, __nv_bfloat16, wmma::col_major> bfh[4], bfl[4];
#pragma unroll
            for (int fm = 0; fm < 2; fm++)
                wmma::load_matrix_sync(afh[fm], ah_sm + (wm0 + fm * 16) * LDA + kk, LDA);
#pragma unroll
            for (int fn = 0; fn < 4; fn++)
                wmma::load_matrix_sync(bfh[fn], wh_sm + (wn0 + fn * 16) * LDA + kk, LDA);
#pragma unroll
            for (int fm = 0; fm < 2; fm++)
#pragma unroll
                for (int fn = 0; fn < 4; fn++)
                    wmma::mma_sync(acc[fm][fn], afh[fm], bfh[fn], acc[fm][fn]);
#pragma unroll
            for (int fm = 0; fm < 2; fm++)
                wmma::load_matrix_sync(afl[fm], al_sm + (wm0 + fm * 16) * LDA + kk, LDA);
#pragma unroll
            for (int fm = 0; fm < 2; fm++)
#pragma unroll
                for (int fn = 0; fn < 4; fn++)
                    wmma::mma_sync(acc[fm][fn], afl[fm], bfh[fn], acc[fm][fn]);
#pragma unroll
            for (int fn = 0; fn < 4; fn++)
                wmma::load_matrix_sync(bfl[fn], wl_sm + (wn0 + fn * 16) * LDA + kk, LDA);
#pragma unroll
            for (int fm = 0; fm < 2; fm++)
#pragma unroll
                for (int fn = 0; fn < 4; fn++)
                    wmma::mma_sync(acc[fm][fn], afh[fm], bfl[fn], acc[fm][fn]);
        }
        __syncthreads();
    }

    // ---- epilogue: frags -> smem -> (bias+gprob) -> scratch (coalesced f4) ----
    float* epi = (float*)smem;
#pragma unroll
    for (int fm = 0; fm < 2; fm++)
#pragma unroll
        for (int fn = 0; fn < 4; fn++)
            wmma::store_matrix_sync(epi + (wm0 + fm * 16) * LDE + wn0 + fn * 16,
                                    acc[fm][fn], LDE, wmma::mem_row_major);
    __syncthreads();

#pragma unroll
    for (int i = 0; i < 16; i++) {
        int idx = i * 256 + t;
        int r  = idx >> 5;
        int c4 = (idx & 31) * 4;
        float4 v = *(float4*)(epi + r * LDE + c4);
        int n = n0 + c4;
        float gp = __ldg(gprob + (size_t)(row0 + r) * 16 + (n >> 6));
        v.x = (v.x + __ldg(bias + n + 0)) * gp;
        v.y = (v.y + __ldg(bias + n + 1)) * gp;
        v.z = (v.z + __ldg(bias + n + 2)) * gp;
        v.w = (v.w + __ldg(bias + n + 3)) * gp;
        *(float4*)(g_scratch + (size_t)(row0 + r) * NCOLS + n) = v;
    }
}

// ---- scatter: 4-row tiles, 6 CTAs/SM, class-outer/row-inner gather (R10 proven) ----
__global__ void __launch_bounds__(256, 6)
mhc_scatter(float* __restrict__ out) {
    extern __shared__ char smem[];
    float* wsm    = (float*)(smem + SC_WSM);
    int*   off_sm = (int*)(smem + SC_OFF);
    int*   src_sm = (int*)(smem + SC_SRC);
    const int t = threadIdx.x;
    const int r0 = blockIdx.x * SROWS;

    for (int i = t; i <= NCLS; i += 256) off_sm[i] = g_cls_off[i];
    for (int i = t; i < NCOLS; i += 256) src_sm[i] = g_cls_src[i];

    const float4* src = (const float4*)(g_scratch + (size_t)r0 * NCOLS);
    float4* dst4 = (float4*)wsm;
#pragma unroll
    for (int i = 0; i < SROWS * NCOLS / 4 / 256; i++)
        dst4[i * 256 + t] = src[i * 256 + t];
    __syncthreads();

    for (int c = t; c < NCLS; c += 256) {
        int s0 = off_sm[c], s1 = off_sm[c + 1];
        float* ocol = out + (size_t)r0 * NCLS + c;
        if (s1 == s0) {
#pragma unroll
            for (int r = 0; r < SROWS; r++) ocol[(size_t)r * NCLS] = 0.f;
        } else if (s1 == s0 + 1) {
            int src0 = src_sm[s0];
#pragma unroll
            for (int r = 0; r < SROWS; r++)
                ocol[(size_t)r * NCLS] = wsm[r * NCOLS + src0];
        } else {
#pragma unroll
            for (int r = 0; r < SROWS; r++) {
                float s = 0.f;
                for (int k = s0; k < s1; k++) s += wsm[r * NCOLS + src_sm[k]];
                ocol[(size_t)r * NCLS] = s;
            }
        }
    }
}

extern "C" void kernel_launch(void* const* d_in, const int* in_sizes, int n_in,
                              void* d_out, int out_size) {
    const float* features = (const float*)d_in[0];
    const float* gprob    = (const float*)d_in[1];
    const float* W        = (const float*)d_in[2];
    const float* bias     = (const float*)d_in[3];
    const int*   labels   = (const int*)d_in[4];
    float* out = (float*)d_out;

    static __nv_bfloat16 *hA, *lA, *hW, *lW;
    static bool init = false;
    if (!init) {
        cudaGetSymbolAddress((void**)&hA, g_Ahi);
        cudaGetSymbolAddress((void**)&lA, g_Alo);
        cudaGetSymbolAddress((void**)&hW, g_Whi);
        cudaGetSymbolAddress((void**)&lW, g_Wlo);
        cudaFuncSetAttribute(mhc_gemm, cudaFuncAttributeMaxDynamicSharedMemorySize, SMEM_GEMM);
        cudaFuncSetAttribute(mhc_scatter, cudaFuncAttributeMaxDynamicSharedMemorySize, SMEM_SCAT);
        init = true;
    }

    prep_kernel<<<1, 1024>>>(labels);
    prep_split<<<A_BLOCKS + (NCOLS * FDIM) / 1024, 256>>>(features, W, hA, lA, hW, lW);

    dim3 grid(NCOLS / BN, B_ROWS / BM);
    mhc_gemm<<<grid, 256, SMEM_GEMM>>>(gprob, bias);
    mhc_scatter<<<B_ROWS / SROWS, 256, SMEM_SCAT>>>(out);
}

// round 12
// speedup vs baseline: 1.1908x; 1.1073x over previous
#include <cuda_runtime.h>
#include <cuda_bf16.h>
#include <mma.h>
#include <cstdint>

using namespace nvcuda;

#define B_ROWS 32768
#define FDIM   512
#define NCOLS  1024
#define NCLS   1000

#define BM 128
#define BN 128
#define BK 32
#define LDA 40               // bf16 smem pitch (80B)
#define LDE 136              // fp32 epilogue pitch
#define NIT 16               // 512/32 (all 3 products per chunk)
#define TILE_B 10240         // one 128x32 bf16 tile @ pitch 80
#define STAGE_BYTES 40960    // Ahi+Alo+Whi+Wlo
#define SMEM_GEMM (2 * STAGE_BYTES)   // 81920

#define NCHUNK 4
#define CROWS  (B_ROWS / NCHUNK)      // 8192 rows per pipeline chunk

// scatter: 4-row tile -> 6 CTAs/SM (measured best)
#define SROWS 4
#define SC_WSM 0                        // [4][1024] f = 16384B
#define SC_OFF 16384                    // int[1001]
#define SC_SRC 20488                    // int[1024]
#define SMEM_SCAT 24584

__device__ int   g_cls_off[NCLS + 1];
__device__ int   g_cls_src[NCOLS];
__device__ __nv_bfloat16 g_Ahi[(size_t)B_ROWS * FDIM];
__device__ __nv_bfloat16 g_Alo[(size_t)B_ROWS * FDIM];
__device__ __nv_bfloat16 g_Whi[NCOLS * FDIM];
__device__ __nv_bfloat16 g_Wlo[NCOLS * FDIM];
__device__ float g_scratch[(size_t)B_ROWS * NCOLS];

__device__ __forceinline__ uint32_t smem_u32(const void* p) {
    uint32_t a;
    asm("{ .reg .u64 t; cvta.to.shared.u64 t, %1; cvt.u32.u64 %0, t; }" : "=r"(a) : "l"(p));
    return a;
}
__device__ __forceinline__ void cp16(uint32_t dst, const void* src) {
    asm volatile("cp.async.cg.shared.global [%0], [%1], 16;" :: "r"(dst), "l"(src) : "memory");
}

// ---- prep: deterministic CSR (atomic fill + per-class sort == sequential order) ----
__global__ void prep_kernel(const int* __restrict__ label_ids) {
    __shared__ int lab[NCOLS];
    __shared__ int cnt[NCLS];
    __shared__ int off[NCLS + 1];
    __shared__ int pos[NCLS];
    __shared__ int srcs[NCOLS];
    int t = threadIdx.x;             // 1024 threads
    lab[t] = label_ids[t];
    if (t < NCLS) cnt[t] = 0;
    __syncthreads();
    atomicAdd(&cnt[lab[t]], 1);
    __syncthreads();
    if (t == 0) {
        int a = 0;
        for (int c = 0; c < NCLS; c++) { off[c] = a; a += cnt[c]; }
        off[NCLS] = a;
    }
    __syncthreads();
    if (t < NCLS) pos[t] = off[t];
    __syncthreads();
    int p = atomicAdd(&pos[lab[t]], 1);   // arbitrary order...
    srcs[p] = t;
    __syncthreads();
    if (t < NCLS) {                        // ...made deterministic by ascending sort
        int s0 = off[t], s1 = off[t + 1];
        for (int i = s0 + 1; i < s1; i++) {
            int v = srcs[i], j = i - 1;
            while (j >= s0 && srcs[j] > v) { srcs[j + 1] = srcs[j]; j--; }
            srcs[j + 1] = v;
        }
    }
    __syncthreads();
    if (t <= NCLS) g_cls_off[t] = off[t];
    g_cls_src[t] = srcs[t];
}

// ---- prep: fp32 -> bf16 hi/lo for A and W in one launch ----
#define A_BLOCKS ((B_ROWS * FDIM) / 1024)
__global__ void prep_split(const float* __restrict__ A, const float* __restrict__ W,
                           __nv_bfloat16* __restrict__ Ahi, __nv_bfloat16* __restrict__ Alo,
                           __nv_bfloat16* __restrict__ Whi, __nv_bfloat16* __restrict__ Wlo) {
    int blk = blockIdx.x;
    const float* src;
    __nv_bfloat16 *hi, *lo;
    size_t i0;
    if (blk < A_BLOCKS) {
        src = A; hi = Ahi; lo = Alo;
        i0 = ((size_t)blk * 256 + threadIdx.x) * 4;
    } else {
        src = W; hi = Whi; lo = Wlo;
        i0 = ((size_t)(blk - A_BLOCKS) * 256 + threadIdx.x) * 4;
    }
    float4 v = *(const float4*)(src + i0);
    __nv_bfloat16 h[4], l[4];
    float x;
    x = v.x; h[0] = __float2bfloat16_rn(x); l[0] = __float2bfloat16_rn(x - __bfloat162float(h[0]));
    x = v.y; h[1] = __float2bfloat16_rn(x); l[1] = __float2bfloat16_rn(x - __bfloat162float(h[1]));
    x = v.z; h[2] = __float2bfloat16_rn(x); l[2] = __float2bfloat16_rn(x - __bfloat162float(h[2]));
    x = v.w; h[3] = __float2bfloat16_rn(x); l[3] = __float2bfloat16_rn(x - __bfloat162float(h[3]));
    *(uint2*)(hi + i0) = *(uint2*)h;
    *(uint2*)(lo + i0) = *(uint2*)l;
}

// ---- GEMM: 128x128, fused 3-product split, double-buffered cp.async (R9 proven) ----
__global__ void __launch_bounds__(256, 2)
mhc_gemm(const float* __restrict__ gprob, const float* __restrict__ bias, int rbase) {
    extern __shared__ char smem[];
    const uint32_t sb = smem_u32(smem);
    const int t   = threadIdx.x;
    const int wid = t >> 5;
    const int n0   = blockIdx.x * BN;
    const int row0 = rbase + blockIdx.y * BM;
    const int wm0 = (wid & 3) * 32;
    const int wn0 = (wid >> 2) * 64;

    wmma::fragment<wmma::accumulator, 16, 16, 16, float> acc[2][4];
#pragma unroll
    for (int fm = 0; fm < 2; fm++)
#pragma unroll
        for (int fn = 0; fn < 4; fn++) wmma::fill_fragment(acc[fm][fn], 0.0f);

    auto issue = [&](int it, int s) {
        if (it < NIT) {
            const char* ah = (const char*)(g_Ahi + (size_t)row0 * FDIM + it * BK);
            const char* al = (const char*)(g_Alo + (size_t)row0 * FDIM + it * BK);
            const char* wh = (const char*)(g_Whi + (size_t)n0 * FDIM + it * BK);
            const char* wl = (const char*)(g_Wlo + (size_t)n0 * FDIM + it * BK);
            uint32_t st = sb + s * STAGE_BYTES;
#pragma unroll
            for (int i = 0; i < 2; i++) {
                int id = i * 256 + t;
                int r = id >> 2, co = (id & 3) * 16;
                size_t go = (size_t)r * 1024 + co;
                uint32_t so = r * 80 + co;
                cp16(st + so,              ah + go);
                cp16(st + TILE_B + so,     al + go);
                cp16(st + 2 * TILE_B + so, wh + go);
                cp16(st + 3 * TILE_B + so, wl + go);
            }
        }
        asm volatile("cp.async.commit_group;" ::: "memory");
    };

    issue(0, 0);
    for (int it = 0; it < NIT; ++it) {
        int s = it & 1;
        issue(it + 1, s ^ 1);
        asm volatile("cp.async.wait_group 1;" ::: "memory");
        __syncthreads();

        const __nv_bfloat16* ah_sm = (const __nv_bfloat16*)(smem + s * STAGE_BYTES);
        const __nv_bfloat16* al_sm = (const __nv_bfloat16*)(smem + s * STAGE_BYTES + TILE_B);
        const __nv_bfloat16* wh_sm = (const __nv_bfloat16*)(smem + s * STAGE_BYTES + 2 * TILE_B);
        const __nv_bfloat16* wl_sm = (const __nv_bfloat16*)(smem + s * STAGE_BYTES + 3 * TILE_B);
#pragma unroll
        for (int kk = 0; kk < BK; kk += 16) {
            wmma::fragment<wmma::matrix_a, 16, 16, 16, __nv_bfloat16, wmma::row_major> afh[2], afl[2];
            wmma::fragment<wmma::matrix_b, 16, 16, 16, __nv_bfloat16, wmma::col_major> bfh[4], bfl[4];
#pragma unroll
            for (int fm = 0; fm < 2; fm++)
                wmma::load_matrix_sync(afh[fm], ah_sm + (wm0 + fm * 16) * LDA + kk, LDA);
#pragma unroll
            for (int fn = 0; fn < 4; fn++)
                wmma::load_matrix_sync(bfh[fn], wh_sm + (wn0 + fn * 16) * LDA + kk, LDA);
#pragma unroll
            for (int fm = 0; fm < 2; fm++)
#pragma unroll
                for (int fn = 0; fn < 4; fn++)
                    wmma::mma_sync(acc[fm][fn], afh[fm], bfh[fn], acc[fm][fn]);
#pragma unroll
            for (int fm = 0; fm < 2; fm++)
                wmma::load_matrix_sync(afl[fm], al_sm + (wm0 + fm * 16) * LDA + kk, LDA);
#pragma unroll
            for (int fm = 0; fm < 2; fm++)
#pragma unroll
                for (int fn = 0; fn < 4; fn++)
                    wmma::mma_sync(acc[fm][fn], afl[fm], bfh[fn], acc[fm][fn]);
#pragma unroll
            for (int fn = 0; fn < 4; fn++)
                wmma::load_matrix_sync(bfl[fn], wl_sm + (wn0 + fn * 16) * LDA + kk, LDA);
#pragma unroll
            for (int fm = 0; fm < 2; fm++)
#pragma unroll
                for (int fn = 0; fn < 4; fn++)
                    wmma::mma_sync(acc[fm][fn], afh[fm], bfl[fn], acc[fm][fn]);
        }
        __syncthreads();
    }

    // ---- epilogue: frags -> smem -> (bias+gprob) -> scratch (coalesced f4) ----
    float* epi = (float*)smem;
#pragma unroll
    for (int fm = 0; fm < 2; fm++)
#pragma unroll
        for (int fn = 0; fn < 4; fn++)
            wmma::store_matrix_sync(epi + (wm0 + fm * 16) * LDE + wn0 + fn * 16,
                                    acc[fm][fn], LDE, wmma::mem_row_major);
    __syncthreads();

#pragma unroll
    for (int i = 0; i < 16; i++) {
        int idx = i * 256 + t;
        int r  = idx >> 5;
        int c4 = (idx & 31) * 4;
        float4 v = *(float4*)(epi + r * LDE + c4);
        int n = n0 + c4;
        float gp = __ldg(gprob + (size_t)(row0 + r) * 16 + (n >> 6));
        v.x = (v.x + __ldg(bias + n + 0)) * gp;
        v.y = (v.y + __ldg(bias + n + 1)) * gp;
        v.z = (v.z + __ldg(bias + n + 2)) * gp;
        v.w = (v.w + __ldg(bias + n + 3)) * gp;
        *(float4*)(g_scratch + (size_t)(row0 + r) * NCOLS + n) = v;
    }
}

// ---- scatter: 4-row tiles, 6 CTAs/SM, class-outer/row-inner gather ----
__global__ void __launch_bounds__(256, 6)
mhc_scatter(float* __restrict__ out, int rbase) {
    extern __shared__ char smem[];
    float* wsm    = (float*)(smem + SC_WSM);
    int*   off_sm = (int*)(smem + SC_OFF);
    int*   src_sm = (int*)(smem + SC_SRC);
    const int t = threadIdx.x;
    const int r0 = rbase + blockIdx.x * SROWS;

    for (int i = t; i <= NCLS; i += 256) off_sm[i] = g_cls_off[i];
    for (int i = t; i < NCOLS; i += 256) src_sm[i] = g_cls_src[i];

    const float4* src = (const float4*)(g_scratch + (size_t)r0 * NCOLS);
    float4* dst4 = (float4*)wsm;
#pragma unroll
    for (int i = 0; i < SROWS * NCOLS / 4 / 256; i++)
        dst4[i * 256 + t] = src[i * 256 + t];
    __syncthreads();

    for (int c = t; c < NCLS; c += 256) {
        int s0 = off_sm[c], s1 = off_sm[c + 1];
        float* ocol = out + (size_t)r0 * NCLS + c;
        if (s1 == s0) {
#pragma unroll
            for (int r = 0; r < SROWS; r++) ocol[(size_t)r * NCLS] = 0.f;
        } else if (s1 == s0 + 1) {
            int src0 = src_sm[s0];
#pragma unroll
            for (int r = 0; r < SROWS; r++)
                ocol[(size_t)r * NCLS] = wsm[r * NCOLS + src0];
        } else {
#pragma unroll
            for (int r = 0; r < SROWS; r++) {
                float s = 0.f;
                for (int k = s0; k < s1; k++) s += wsm[r * NCOLS + src_sm[k]];
                ocol[(size_t)r * NCLS] = s;
            }
        }
    }
}

extern "C" void kernel_launch(void* const* d_in, const int* in_sizes, int n_in,
                              void* d_out, int out_size) {
    const float* features = (const float*)d_in[0];
    const float* gprob    = (const float*)d_in[1];
    const float* W        = (const float*)d_in[2];
    const float* bias     = (const float*)d_in[3];
    const int*   labels   = (const int*)d_in[4];
    float* out = (float*)d_out;

    static __nv_bfloat16 *hA, *lA, *hW, *lW;
    static cudaStream_t s2;
    static cudaEvent_t evF, evG[NCHUNK], evJ;
    static bool init = false;
    if (!init) {
        cudaGetSymbolAddress((void**)&hA, g_Ahi);
        cudaGetSymbolAddress((void**)&lA, g_Alo);
        cudaGetSymbolAddress((void**)&hW, g_Whi);
        cudaGetSymbolAddress((void**)&lW, g_Wlo);
        cudaFuncSetAttribute(mhc_gemm, cudaFuncAttributeMaxDynamicSharedMemorySize, SMEM_GEMM);
        cudaFuncSetAttribute(mhc_scatter, cudaFuncAttributeMaxDynamicSharedMemorySize, SMEM_SCAT);
        cudaStreamCreateWithFlags(&s2, cudaStreamNonBlocking);
        cudaEventCreateWithFlags(&evF, cudaEventDisableTiming);
        for (int c = 0; c < NCHUNK; c++)
            cudaEventCreateWithFlags(&evG[c], cudaEventDisableTiming);
        cudaEventCreateWithFlags(&evJ, cudaEventDisableTiming);
        init = true;
    }

    // fork: side stream runs the (independent) CSR prep
    cudaEventRecord(evF, 0);
    cudaStreamWaitEvent(s2, evF, 0);
    prep_kernel<<<1, 1024, 0, s2>>>(labels);

    // main stream: split, then GEMM in row chunks
    prep_split<<<A_BLOCKS + (NCOLS * FDIM) / 1024, 256>>>(features, W, hA, lA, hW, lW);
    for (int c = 0; c < NCHUNK; c++) {
        dim3 grid(NCOLS / BN, CROWS / BM);
        mhc_gemm<<<grid, 256, SMEM_GEMM>>>(gprob, bias, c * CROWS);
        cudaEventRecord(evG[c], 0);
    }

    // side stream: scatter chunk c as soon as its GEMM chunk lands
    for (int c = 0; c < NCHUNK; c++) {
        cudaStreamWaitEvent(s2, evG[c], 0);
        mhc_scatter<<<CROWS / SROWS, 256, SMEM_SCAT, s2>>>(out, c * CROWS);
    }

    // join
    cudaEventRecord(evJ, s2);
    cudaStreamWaitEvent(0, evJ, 0);
}

// round 13
// speedup vs baseline: 1.2018x; 1.0092x over previous
#include <cuda_runtime.h>
#include <cuda_bf16.h>
#include <mma.h>
#include <cstdint>

using namespace nvcuda;

#define B_ROWS 32768
#define FDIM   512
#define NCOLS  1024
#define NCLS   1000

#define BM 128
#define BN 128
#define BK 32
#define LDA 40               // bf16 smem pitch (80B)
#define LDE 136              // fp32 epilogue pitch
#define NIT 16               // 512/32 (all 3 products per chunk)
#define TILE_B 10240         // one 128x32 bf16 tile @ pitch 80
#define STAGE_BYTES 40960    // Ahi+Alo+Whi+Wlo
#define SMEM_GEMM (2 * STAGE_BYTES)   // 81920

#define NCHUNK 8
#define CROWS  (B_ROWS / NCHUNK)      // 4096 rows per pipeline chunk

// scatter: 4-row tile -> 6 CTAs/SM (measured best)
#define SROWS 4
#define SC_WSM 0                        // [4][1024] f = 16384B
#define SC_OFF 16384                    // int[1001]
#define SC_SRC 20488                    // int[1024]
#define SMEM_SCAT 24584

__device__ int   g_cls_off[NCLS + 1];
__device__ int   g_cls_src[NCOLS];
__device__ __nv_bfloat16 g_Ahi[(size_t)B_ROWS * FDIM];
__device__ __nv_bfloat16 g_Alo[(size_t)B_ROWS * FDIM];
__device__ __nv_bfloat16 g_Whi[NCOLS * FDIM];
__device__ __nv_bfloat16 g_Wlo[NCOLS * FDIM];
__device__ float g_scratch[(size_t)B_ROWS * NCOLS];

__device__ __forceinline__ uint32_t smem_u32(const void* p) {
    uint32_t a;
    asm("{ .reg .u64 t; cvta.to.shared.u64 t, %1; cvt.u32.u64 %0, t; }" : "=r"(a) : "l"(p));
    return a;
}
__device__ __forceinline__ void cp16(uint32_t dst, const void* src) {
    asm volatile("cp.async.cg.shared.global [%0], [%1], 16;" :: "r"(dst), "l"(src) : "memory");
}

// ---- prep: deterministic CSR (atomic fill + per-class sort == sequential order) ----
__global__ void prep_kernel(const int* __restrict__ label_ids) {
    __shared__ int lab[NCOLS];
    __shared__ int cnt[NCLS];
    __shared__ int off[NCLS + 1];
    __shared__ int pos[NCLS];
    __shared__ int srcs[NCOLS];
    int t = threadIdx.x;             // 1024 threads
    lab[t] = label_ids[t];
    if (t < NCLS) cnt[t] = 0;
    __syncthreads();
    atomicAdd(&cnt[lab[t]], 1);
    __syncthreads();
    if (t == 0) {
        int a = 0;
        for (int c = 0; c < NCLS; c++) { off[c] = a; a += cnt[c]; }
        off[NCLS] = a;
    }
    __syncthreads();
    if (t < NCLS) pos[t] = off[t];
    __syncthreads();
    int p = atomicAdd(&pos[lab[t]], 1);   // arbitrary order...
    srcs[p] = t;
    __syncthreads();
    if (t < NCLS) {                        // ...made deterministic by ascending sort
        int s0 = off[t], s1 = off[t + 1];
        for (int i = s0 + 1; i < s1; i++) {
            int v = srcs[i], j = i - 1;
            while (j >= s0 && srcs[j] > v) { srcs[j + 1] = srcs[j]; j--; }
            srcs[j + 1] = v;
        }
    }
    __syncthreads();
    if (t <= NCLS) g_cls_off[t] = off[t];
    g_cls_src[t] = srcs[t];
}

// ---- prep: fp32 -> bf16 hi/lo for A and W in one launch ----
#define A_BLOCKS ((B_ROWS * FDIM) / 1024)
__global__ void prep_split(const float* __restrict__ A, const float* __restrict__ W,
                           __nv_bfloat16* __restrict__ Ahi, __nv_bfloat16* __restrict__ Alo,
                           __nv_bfloat16* __restrict__ Whi, __nv_bfloat16* __restrict__ Wlo) {
    int blk = blockIdx.x;
    const float* src;
    __nv_bfloat16 *hi, *lo;
    size_t i0;
    if (blk < A_BLOCKS) {
        src = A; hi = Ahi; lo = Alo;
        i0 = ((size_t)blk * 256 + threadIdx.x) * 4;
    } else {
        src = W; hi = Whi; lo = Wlo;
        i0 = ((size_t)(blk - A_BLOCKS) * 256 + threadIdx.x) * 4;
    }
    float4 v = *(const float4*)(src + i0);
    __nv_bfloat16 h[4], l[4];
    float x;
    x = v.x; h[0] = __float2bfloat16_rn(x); l[0] = __float2bfloat16_rn(x - __bfloat162float(h[0]));
    x = v.y; h[1] = __float2bfloat16_rn(x); l[1] = __float2bfloat16_rn(x - __bfloat162float(h[1]));
    x = v.z; h[2] = __float2bfloat16_rn(x); l[2] = __float2bfloat16_rn(x - __bfloat162float(h[2]));
    x = v.w; h[3] = __float2bfloat16_rn(x); l[3] = __float2bfloat16_rn(x - __bfloat162float(h[3]));
    *(uint2*)(hi + i0) = *(uint2*)h;
    *(uint2*)(lo + i0) = *(uint2*)l;
}

// ---- GEMM: 128x128, fused 3-product split, double-buffered cp.async (R9 proven) ----
__global__ void __launch_bounds__(256, 2)
mhc_gemm(const float* __restrict__ gprob, const float* __restrict__ bias, int rbase) {
    extern __shared__ char smem[];
    const uint32_t sb = smem_u32(smem);
    const int t   = threadIdx.x;
    const int wid = t >> 5;
    const int n0   = blockIdx.x * BN;
    const int row0 = rbase + blockIdx.y * BM;
    const int wm0 = (wid & 3) * 32;
    const int wn0 = (wid >> 2) * 64;

    wmma::fragment<wmma::accumulator, 16, 16, 16, float> acc[2][4];
#pragma unroll
    for (int fm = 0; fm < 2; fm++)
#pragma unroll
        for (int fn = 0; fn < 4; fn++) wmma::fill_fragment(acc[fm][fn], 0.0f);

    auto issue = [&](int it, int s) {
        if (it < NIT) {
            const char* ah = (const char*)(g_Ahi + (size_t)row0 * FDIM + it * BK);
            const char* al = (const char*)(g_Alo + (size_t)row0 * FDIM + it * BK);
            const char* wh = (const char*)(g_Whi + (size_t)n0 * FDIM + it * BK);
            const char* wl = (const char*)(g_Wlo + (size_t)n0 * FDIM + it * BK);
            uint32_t st = sb + s * STAGE_BYTES;
#pragma unroll
            for (int i = 0; i < 2; i++) {
                int id = i * 256 + t;
                int r = id >> 2, co = (id & 3) * 16;
                size_t go = (size_t)r * 1024 + co;
                uint32_t so = r * 80 + co;
                cp16(st + so,              ah + go);
                cp16(st + TILE_B + so,     al + go);
                cp16(st + 2 * TILE_B + so, wh + go);
                cp16(st + 3 * TILE_B + so, wl + go);
            }
        }
        asm volatile("cp.async.commit_group;" ::: "memory");
    };

    issue(0, 0);
    for (int it = 0; it < NIT; ++it) {
        int s = it & 1;
        issue(it + 1, s ^ 1);
        asm volatile("cp.async.wait_group 1;" ::: "memory");
        __syncthreads();

        const __nv_bfloat16* ah_sm = (const __nv_bfloat16*)(smem + s * STAGE_BYTES);
        const __nv_bfloat16* al_sm = (const __nv_bfloat16*)(smem + s * STAGE_BYTES + TILE_B);
        const __nv_bfloat16* wh_sm = (const __nv_bfloat16*)(smem + s * STAGE_BYTES + 2 * TILE_B);
        const __nv_bfloat16* wl_sm = (const __nv_bfloat16*)(smem + s * STAGE_BYTES + 3 * TILE_B);
#pragma unroll
        for (int kk = 0; kk < BK; kk += 16) {
            wmma::fragment<wmma::matrix_a, 16, 16, 16, __nv_bfloat16, wmma::row_major> afh[2], afl[2];
            wmma::fragment<wmma::matrix_b, 16, 16, 16, __nv_bfloat16, wmma::col_major> bfh[4], bfl[4];
#pragma unroll
            for (int fm = 0; fm < 2; fm++)
                wmma::load_matrix_sync(afh[fm], ah_sm + (wm0 + fm * 16) * LDA + kk, LDA);
#pragma unroll
            for (int fn = 0; fn < 4; fn++)
                wmma::load_matrix_sync(bfh[fn], wh_sm + (wn0 + fn * 16) * LDA + kk, LDA);
#pragma unroll
            for (int fm = 0; fm < 2; fm++)
#pragma unroll
                for (int fn = 0; fn < 4; fn++)
                    wmma::mma_sync(acc[fm][fn], afh[fm], bfh[fn], acc[fm][fn]);
#pragma unroll
            for (int fm = 0; fm < 2; fm++)
                wmma::load_matrix_sync(afl[fm], al_sm + (wm0 + fm * 16) * LDA + kk, LDA);
#pragma unroll
            for (int fm = 0; fm < 2; fm++)
#pragma unroll
                for (int fn = 0; fn < 4; fn++)
                    wmma::mma_sync(acc[fm][fn], afl[fm], bfh[fn], acc[fm][fn]);
#pragma unroll
            for (int fn = 0; fn < 4; fn++)
                wmma::load_matrix_sync(bfl[fn], wl_sm + (wn0 + fn * 16) * LDA + kk, LDA);
#pragma unroll
            for (int fm = 0; fm < 2; fm++)
#pragma unroll
                for (int fn = 0; fn < 4; fn++)
                    wmma::mma_sync(acc[fm][fn], afh[fm], bfl[fn], acc[fm][fn]);
        }
        __syncthreads();
    }

    // ---- epilogue: frags -> smem -> (bias+gprob) -> scratch (coalesced f4) ----
    float* epi = (float*)smem;
#pragma unroll
    for (int fm = 0; fm < 2; fm++)
#pragma unroll
        for (int fn = 0; fn < 4; fn++)
            wmma::store_matrix_sync(epi + (wm0 + fm * 16) * LDE + wn0 + fn * 16,
                                    acc[fm][fn], LDE, wmma::mem_row_major);
    __syncthreads();

#pragma unroll
    for (int i = 0; i < 16; i++) {
        int idx = i * 256 + t;
        int r  = idx >> 5;
        int c4 = (idx & 31) * 4;
        float4 v = *(float4*)(epi + r * LDE + c4);
        int n = n0 + c4;
        float gp = __ldg(gprob + (size_t)(row0 + r) * 16 + (n >> 6));
        v.x = (v.x + __ldg(bias + n + 0)) * gp;
        v.y = (v.y + __ldg(bias + n + 1)) * gp;
        v.z = (v.z + __ldg(bias + n + 2)) * gp;
        v.w = (v.w + __ldg(bias + n + 3)) * gp;
        *(float4*)(g_scratch + (size_t)(row0 + r) * NCOLS + n) = v;
    }
}

// ---- scatter: 4-row tiles, 6 CTAs/SM, class-outer/row-inner gather ----
__global__ void __launch_bounds__(256, 6)
mhc_scatter(float* __restrict__ out, int rbase) {
    extern __shared__ char smem[];
    float* wsm    = (float*)(smem + SC_WSM);
    int*   off_sm = (int*)(smem + SC_OFF);
    int*   src_sm = (int*)(smem + SC_SRC);
    const int t = threadIdx.x;
    const int r0 = rbase + blockIdx.x * SROWS;

    for (int i = t; i <= NCLS; i += 256) off_sm[i] = g_cls_off[i];
    for (int i = t; i < NCOLS; i += 256) src_sm[i] = g_cls_src[i];

    const float4* src = (const float4*)(g_scratch + (size_t)r0 * NCOLS);
    float4* dst4 = (float4*)wsm;
#pragma unroll
    for (int i = 0; i < SROWS * NCOLS / 4 / 256; i++)
        dst4[i * 256 + t] = src[i * 256 + t];
    __syncthreads();

    for (int c = t; c < NCLS; c += 256) {
        int s0 = off_sm[c], s1 = off_sm[c + 1];
        float* ocol = out + (size_t)r0 * NCLS + c;
        if (s1 == s0) {
#pragma unroll
            for (int r = 0; r < SROWS; r++) ocol[(size_t)r * NCLS] = 0.f;
        } else if (s1 == s0 + 1) {
            int src0 = src_sm[s0];
#pragma unroll
            for (int r = 0; r < SROWS; r++)
                ocol[(size_t)r * NCLS] = wsm[r * NCOLS + src0];
        } else {
#pragma unroll
            for (int r = 0; r < SROWS; r++) {
                float s = 0.f;
                for (int k = s0; k < s1; k++) s += wsm[r * NCOLS + src_sm[k]];
                ocol[(size_t)r * NCLS] = s;
            }
        }
    }
}

extern "C" void kernel_launch(void* const* d_in, const int* in_sizes, int n_in,
                              void* d_out, int out_size) {
    const float* features = (const float*)d_in[0];
    const float* gprob    = (const float*)d_in[1];
    const float* W        = (const float*)d_in[2];
    const float* bias     = (const float*)d_in[3];
    const int*   labels   = (const int*)d_in[4];
    float* out = (float*)d_out;

    static __nv_bfloat16 *hA, *lA, *hW, *lW;
    static cudaStream_t s2, sG;
    static cudaEvent_t evF, evS, evG[NCHUNK], evJ, evJG;
    static bool init = false;
    if (!init) {
        cudaGetSymbolAddress((void**)&hA, g_Ahi);
        cudaGetSymbolAddress((void**)&lA, g_Alo);
        cudaGetSymbolAddress((void**)&hW, g_Whi);
        cudaGetSymbolAddress((void**)&lW, g_Wlo);
        cudaFuncSetAttribute(mhc_gemm, cudaFuncAttributeMaxDynamicSharedMemorySize, SMEM_GEMM);
        cudaFuncSetAttribute(mhc_scatter, cudaFuncAttributeMaxDynamicSharedMemorySize, SMEM_SCAT);
        cudaStreamCreateWithFlags(&s2, cudaStreamNonBlocking);
        cudaStreamCreateWithFlags(&sG, cudaStreamNonBlocking);
        cudaEventCreateWithFlags(&evF, cudaEventDisableTiming);
        cudaEventCreateWithFlags(&evS, cudaEventDisableTiming);
        for (int c = 0; c < NCHUNK; c++)
            cudaEventCreateWithFlags(&evG[c], cudaEventDisableTiming);
        cudaEventCreateWithFlags(&evJ, cudaEventDisableTiming);
        cudaEventCreateWithFlags(&evJG, cudaEventDisableTiming);
        init = true;
    }

    // fork: side stream runs the (independent) CSR prep
    cudaEventRecord(evF, 0);
    cudaStreamWaitEvent(s2, evF, 0);
    prep_kernel<<<1, 1024, 0, s2>>>(labels);

    // main stream: hi/lo split, then GEMM chunks alternating across two streams
    prep_split<<<A_BLOCKS + (NCOLS * FDIM) / 1024, 256>>>(features, W, hA, lA, hW, lW);
    cudaEventRecord(evS, 0);
    cudaStreamWaitEvent(sG, evS, 0);

    for (int c = 0; c < NCHUNK; c++) {
        cudaStream_t gs = (c & 1) ? sG : 0;      // stream 0 already ordered after prep_split
        dim3 grid(NCOLS / BN, CROWS / BM);
        mhc_gemm<<<grid, 256, SMEM_GEMM, gs>>>(gprob, bias, c * CROWS);
        cudaEventRecord(evG[c], gs);
        cudaStreamWaitEvent(s2, evG[c], 0);
        mhc_scatter<<<CROWS / SROWS, 256, SMEM_SCAT, s2>>>(out, c * CROWS);
    }

    // join both side streams back into stream 0
    cudaEventRecord(evJ, s2);
    cudaStreamWaitEvent(0, evJ, 0);
    cudaEventRecord(evJG, sG);
    cudaStreamWaitEvent(0, evJG, 0);
}

// round 14
// speedup vs baseline: 1.2594x; 1.0479x over previous
#include <cuda_runtime.h>
#include <cuda_bf16.h>
#include <mma.h>
#include <cstdint>

using namespace nvcuda;

#define B_ROWS 32768
#define FDIM   512
#define NCOLS  1024
#define NCLS   1000

#define BM 128
#define BN 128
#define BK 32
#define LDA 40               // bf16 smem pitch (80B)
#define LDE 136              // fp32 epilogue pitch
#define NIT 16               // 512/32 (all 3 products per chunk)
#define TILE_B 10240         // one 128x32 bf16 tile @ pitch 80
#define STAGE_BYTES 40960    // Ahi+Alo+Whi+Wlo
#define SMEM_GEMM (2 * STAGE_BYTES)   // 81920

#define NCHUNK 8
#define CROWS  (B_ROWS / NCHUNK)      // 4096 rows per pipeline chunk

// scatter: 4-row tile -> 6 CTAs/SM (measured best)
#define SROWS 4
#define SC_WSM 0                        // [4][1024] f = 16384B
#define SC_OFF 16384                    // int[1001]
#define SC_SRC 20488                    // int[1024]
#define SMEM_SCAT 24584

__device__ int   g_cls_off[NCLS + 1];
__device__ int   g_cls_src[NCOLS];
__device__ __nv_bfloat16 g_Ahi[(size_t)B_ROWS * FDIM];
__device__ __nv_bfloat16 g_Alo[(size_t)B_ROWS * FDIM];
__device__ __nv_bfloat16 g_Whi[NCOLS * FDIM];
__device__ __nv_bfloat16 g_Wlo[NCOLS * FDIM];
__device__ float g_scratch[(size_t)B_ROWS * NCOLS];

__device__ __forceinline__ uint32_t smem_u32(const void* p) {
    uint32_t a;
    asm("{ .reg .u64 t; cvta.to.shared.u64 t, %1; cvt.u32.u64 %0, t; }" : "=r"(a) : "l"(p));
    return a;
}
__device__ __forceinline__ void cp16(uint32_t dst, const void* src) {
    asm volatile("cp.async.cg.shared.global [%0], [%1], 16;" :: "r"(dst), "l"(src) : "memory");
}

// ---- prep: deterministic CSR (atomic fill + per-class sort == sequential order) ----
__global__ void prep_kernel(const int* __restrict__ label_ids) {
    __shared__ int lab[NCOLS];
    __shared__ int cnt[NCLS];
    __shared__ int off[NCLS + 1];
    __shared__ int pos[NCLS];
    __shared__ int srcs[NCOLS];
    int t = threadIdx.x;             // 1024 threads
    lab[t] = label_ids[t];
    if (t < NCLS) cnt[t] = 0;
    __syncthreads();
    atomicAdd(&cnt[lab[t]], 1);
    __syncthreads();
    if (t == 0) {
        int a = 0;
        for (int c = 0; c < NCLS; c++) { off[c] = a; a += cnt[c]; }
        off[NCLS] = a;
    }
    __syncthreads();
    if (t < NCLS) pos[t] = off[t];
    __syncthreads();
    int p = atomicAdd(&pos[lab[t]], 1);   // arbitrary order...
    srcs[p] = t;
    __syncthreads();
    if (t < NCLS) {                        // ...made deterministic by ascending sort
        int s0 = off[t], s1 = off[t + 1];
        for (int i = s0 + 1; i < s1; i++) {
            int v = srcs[i], j = i - 1;
            while (j >= s0 && srcs[j] > v) { srcs[j + 1] = srcs[j]; j--; }
            srcs[j + 1] = v;
        }
    }
    __syncthreads();
    if (t <= NCLS) g_cls_off[t] = off[t];
    g_cls_src[t] = srcs[t];
}

// ---- prep: fp32 -> bf16 hi/lo ----
__device__ __forceinline__ void split4(const float* __restrict__ src, size_t i0,
                                       __nv_bfloat16* __restrict__ hi,
                                       __nv_bfloat16* __restrict__ lo) {
    float4 v = *(const float4*)(src + i0);
    __nv_bfloat16 h[4], l[4];
    float x;
    x = v.x; h[0] = __float2bfloat16_rn(x); l[0] = __float2bfloat16_rn(x - __bfloat162float(h[0]));
    x = v.y; h[1] = __float2bfloat16_rn(x); l[1] = __float2bfloat16_rn(x - __bfloat162float(h[1]));
    x = v.z; h[2] = __float2bfloat16_rn(x); l[2] = __float2bfloat16_rn(x - __bfloat162float(h[2]));
    x = v.w; h[3] = __float2bfloat16_rn(x); l[3] = __float2bfloat16_rn(x - __bfloat162float(h[3]));
    *(uint2*)(hi + i0) = *(uint2*)h;
    *(uint2*)(lo + i0) = *(uint2*)l;
}

__global__ void prep_split_w(const float* __restrict__ W,
                             __nv_bfloat16* __restrict__ Whi, __nv_bfloat16* __restrict__ Wlo) {
    size_t i0 = ((size_t)blockIdx.x * 256 + threadIdx.x) * 4;
    split4(W, i0, Whi, Wlo);
}

__global__ void prep_split_a(const float* __restrict__ A,
                             __nv_bfloat16* __restrict__ Ahi, __nv_bfloat16* __restrict__ Alo,
                             int rbase) {
    size_t i0 = (size_t)rbase * FDIM + ((size_t)blockIdx.x * 256 + threadIdx.x) * 4;
    split4(A, i0, Ahi, Alo);
}

// ---- GEMM: 128x128, fused 3-product split, double-buffered cp.async (R9 proven) ----
__global__ void __launch_bounds__(256, 2)
mhc_gemm(const float* __restrict__ gprob, const float* __restrict__ bias, int rbase) {
    extern __shared__ char smem[];
    const uint32_t sb = smem_u32(smem);
    const int t   = threadIdx.x;
    const int wid = t >> 5;
    const int n0   = blockIdx.x * BN;
    const int row0 = rbase + blockIdx.y * BM;
    const int wm0 = (wid & 3) * 32;
    const int wn0 = (wid >> 2) * 64;

    wmma::fragment<wmma::accumulator, 16, 16, 16, float> acc[2][4];
#pragma unroll
    for (int fm = 0; fm < 2; fm++)
#pragma unroll
        for (int fn = 0; fn < 4; fn++) wmma::fill_fragment(acc[fm][fn], 0.0f);

    auto issue = [&](int it, int s) {
        if (it < NIT) {
            const char* ah = (const char*)(g_Ahi + (size_t)row0 * FDIM + it * BK);
            const char* al = (const char*)(g_Alo + (size_t)row0 * FDIM + it * BK);
            const char* wh = (const char*)(g_Whi + (size_t)n0 * FDIM + it * BK);
            const char* wl = (const char*)(g_Wlo + (size_t)n0 * FDIM + it * BK);
            uint32_t st = sb + s * STAGE_BYTES;
#pragma unroll
            for (int i = 0; i < 2; i++) {
                int id = i * 256 + t;
                int r = id >> 2, co = (id & 3) * 16;
                size_t go = (size_t)r * 1024 + co;
                uint32_t so = r * 80 + co;
                cp16(st + so,              ah + go);
                cp16(st + TILE_B + so,     al + go);
                cp16(st + 2 * TILE_B + so, wh + go);
                cp16(st + 3 * TILE_B + so, wl + go);
            }
        }
        asm volatile("cp.async.commit_group;" ::: "memory");
    };

    issue(0, 0);
    for (int it = 0; it < NIT; ++it) {
        int s = it & 1;
        issue(it + 1, s ^ 1);
        asm volatile("cp.async.wait_group 1;" ::: "memory");
        __syncthreads();

        const __nv_bfloat16* ah_sm = (const __nv_bfloat16*)(smem + s * STAGE_BYTES);
        const __nv_bfloat16* al_sm = (const __nv_bfloat16*)(smem + s * STAGE_BYTES + TILE_B);
        const __nv_bfloat16* wh_sm = (const __nv_bfloat16*)(smem + s * STAGE_BYTES + 2 * TILE_B);
        const __nv_bfloat16* wl_sm = (const __nv_bfloat16*)(smem + s * STAGE_BYTES + 3 * TILE_B);
#pragma unroll
        for (int kk = 0; kk < BK; kk += 16) {
            wmma::fragment<wmma::matrix_a, 16, 16, 16, __nv_bfloat16, wmma::row_major> afh[2], afl[2];
            wmma::fragment<wmma::matrix_b, 16, 16, 16, __nv_bfloat16, wmma::col_major> bfh[4], bfl[4];
#pragma unroll
            for (int fm = 0; fm < 2; fm++)
                wmma::load_matrix_sync(afh[fm], ah_sm + (wm0 + fm * 16) * LDA + kk, LDA);
#pragma unroll
            for (int fn = 0; fn < 4; fn++)
                wmma::load_matrix_sync(bfh[fn], wh_sm + (wn0 + fn * 16) * LDA + kk, LDA);
#pragma unroll
            for (int fm = 0; fm < 2; fm++)
#pragma unroll
                for (int fn = 0; fn < 4; fn++)
                    wmma::mma_sync(acc[fm][fn], afh[fm], bfh[fn], acc[fm][fn]);
#pragma unroll
            for (int fm = 0; fm < 2; fm++)
                wmma::load_matrix_sync(afl[fm], al_sm + (wm0 + fm * 16) * LDA + kk, LDA);
#pragma unroll
            for (int fm = 0; fm < 2; fm++)
#pragma unroll
                for (int fn = 0; fn < 4; fn++)
                    wmma::mma_sync(acc[fm][fn], afl[fm], bfh[fn], acc[fm][fn]);
#pragma unroll
            for (int fn = 0; fn < 4; fn++)
                wmma::load_matrix_sync(bfl[fn], wl_sm + (wn0 + fn * 16) * LDA + kk, LDA);
#pragma unroll
            for (int fm = 0; fm < 2; fm++)
#pragma unroll
                for (int fn = 0; fn < 4; fn++)
                    wmma::mma_sync(acc[fm][fn], afh[fm], bfl[fn], acc[fm][fn]);
        }
        __syncthreads();
    }

    // ---- epilogue: frags -> smem -> (bias+gprob) -> scratch (coalesced f4) ----
    float* epi = (float*)smem;
#pragma unroll
    for (int fm = 0; fm < 2; fm++)
#pragma unroll
        for (int fn = 0; fn < 4; fn++)
            wmma::store_matrix_sync(epi + (wm0 + fm * 16) * LDE + wn0 + fn * 16,
                                    acc[fm][fn], LDE, wmma::mem_row_major);
    __syncthreads();

#pragma unroll
    for (int i = 0; i < 16; i++) {
        int idx = i * 256 + t;
        int r  = idx >> 5;
        int c4 = (idx & 31) * 4;
        float4 v = *(float4*)(epi + r * LDE + c4);
        int n = n0 + c4;
        float gp = __ldg(gprob + (size_t)(row0 + r) * 16 + (n >> 6));
        v.x = (v.x + __ldg(bias + n + 0)) * gp;
        v.y = (v.y + __ldg(bias + n + 1)) * gp;
        v.z = (v.z + __ldg(bias + n + 2)) * gp;
        v.w = (v.w + __ldg(bias + n + 3)) * gp;
        *(float4*)(g_scratch + (size_t)(row0 + r) * NCOLS + n) = v;
    }
}

// ---- scatter: 4-row tiles, 6 CTAs/SM, class-outer/row-inner gather ----
__global__ void __launch_bounds__(256, 6)
mhc_scatter(float* __restrict__ out, int rbase) {
    extern __shared__ char smem[];
    float* wsm    = (float*)(smem + SC_WSM);
    int*   off_sm = (int*)(smem + SC_OFF);
    int*   src_sm = (int*)(smem + SC_SRC);
    const int t = threadIdx.x;
    const int r0 = rbase + blockIdx.x * SROWS;

    for (int i = t; i <= NCLS; i += 256) off_sm[i] = g_cls_off[i];
    for (int i = t; i < NCOLS; i += 256) src_sm[i] = g_cls_src[i];

    const float4* src = (const float4*)(g_scratch + (size_t)r0 * NCOLS);
    float4* dst4 = (float4*)wsm;
#pragma unroll
    for (int i = 0; i < SROWS * NCOLS / 4 / 256; i++)
        dst4[i * 256 + t] = src[i * 256 + t];
    __syncthreads();

    for (int c = t; c < NCLS; c += 256) {
        int s0 = off_sm[c], s1 = off_sm[c + 1];
        float* ocol = out + (size_t)r0 * NCLS + c;
        if (s1 == s0) {
#pragma unroll
            for (int r = 0; r < SROWS; r++) ocol[(size_t)r * NCLS] = 0.f;
        } else if (s1 == s0 + 1) {
            int src0 = src_sm[s0];
#pragma unroll
            for (int r = 0; r < SROWS; r++)
                ocol[(size_t)r * NCLS] = wsm[r * NCOLS + src0];
        } else {
#pragma unroll
            for (int r = 0; r < SROWS; r++) {
                float s = 0.f;
                for (int k = s0; k < s1; k++) s += wsm[r * NCOLS + src_sm[k]];
                ocol[(size_t)r * NCLS] = s;
            }
        }
    }
}

extern "C" void kernel_launch(void* const* d_in, const int* in_sizes, int n_in,
                              void* d_out, int out_size) {
    const float* features = (const float*)d_in[0];
    const float* gprob    = (const float*)d_in[1];
    const float* W        = (const float*)d_in[2];
    const float* bias     = (const float*)d_in[3];
    const int*   labels   = (const int*)d_in[4];
    float* out = (float*)d_out;

    static __nv_bfloat16 *hA, *lA, *hW, *lW;
    static cudaStream_t s2, sG;
    static cudaEvent_t evF, evS, evG[NCHUNK], evJ, evJG;
    static bool init = false;
    if (!init) {
        cudaGetSymbolAddress((void**)&hA, g_Ahi);
        cudaGetSymbolAddress((void**)&lA, g_Alo);
        cudaGetSymbolAddress((void**)&hW, g_Whi);
        cudaGetSymbolAddress((void**)&lW, g_Wlo);
        cudaFuncSetAttribute(mhc_gemm, cudaFuncAttributeMaxDynamicSharedMemorySize, SMEM_GEMM);
        cudaFuncSetAttribute(mhc_scatter, cudaFuncAttributeMaxDynamicSharedMemorySize, SMEM_SCAT);
        cudaStreamCreateWithFlags(&s2, cudaStreamNonBlocking);
        cudaStreamCreateWithFlags(&sG, cudaStreamNonBlocking);
        cudaEventCreateWithFlags(&evF, cudaEventDisableTiming);
        cudaEventCreateWithFlags(&evS, cudaEventDisableTiming);
        for (int c = 0; c < NCHUNK; c++)
            cudaEventCreateWithFlags(&evG[c], cudaEventDisableTiming);
        cudaEventCreateWithFlags(&evJ, cudaEventDisableTiming);
        cudaEventCreateWithFlags(&evJG, cudaEventDisableTiming);
        init = true;
    }

    // fork: side stream runs the (independent) CSR prep
    cudaEventRecord(evF, 0);
    cudaStreamWaitEvent(s2, evF, 0);
    prep_kernel<<<1, 1024, 0, s2>>>(labels);

    // W hi/lo split up front (small); A splits are per-chunk, pipelined
    prep_split_w<<<(NCOLS * FDIM) / 1024, 256>>>(W, hW, lW);
    cudaEventRecord(evS, 0);
    cudaStreamWaitEvent(sG, evS, 0);

    for (int c = 0; c < NCHUNK; c++) {
        cudaStream_t gs = (c & 1) ? sG : 0;      // stream 0 already ordered after prep_split_w
        prep_split_a<<<(CROWS * FDIM) / 1024, 256, 0, gs>>>(features, hA, lA, c * CROWS);
        dim3 grid(NCOLS / BN, CROWS / BM);
        mhc_gemm<<<grid, 256, SMEM_GEMM, gs>>>(gprob, bias, c * CROWS);
        cudaEventRecord(evG[c], gs);
        cudaStreamWaitEvent(s2, evG[c], 0);
        mhc_scatter<<<CROWS / SROWS, 256, SMEM_SCAT, s2>>>(out, c * CROWS);
    }

    // join both side streams back into stream 0
    cudaEventRecord(evJ, s2);
    cudaStreamWaitEvent(0, evJ, 0);
    cudaEventRecord(evJG, sG);
    cudaStreamWaitEvent(0, evJG, 0);
}

// round 15
// speedup vs baseline: 1.7125x; 1.3598x over previous
#include <cuda_runtime.h>
#include <cuda_fp16.h>
#include <mma.h>
#include <cstdint>

using namespace nvcuda;

#define B_ROWS 32768
#define FDIM   512
#define NCOLS  1024
#define NCLS   1000

#define BM 128
#define BN 128
#define BK 32
#define LDA 40               // fp16 smem pitch (80B)
#define LDE 136              // fp32 epilogue pitch
#define NIT 16               // 512/32
#define TILE_B 10240         // one 128x32 fp16 tile @ pitch 80
#define STAGE_BYTES 30720    // Ah + Wh + Wl
#define SMEM_GEMM 69632      // max(2*STAGE_BYTES=61440, epilogue 128*136*4)

#define NCHUNK 8
#define CROWS  (B_ROWS / NCHUNK)

// scatter: 4-row tile -> 6 CTAs/SM (measured best)
#define SROWS 4
#define SC_WSM 0
#define SC_OFF 16384
#define SC_SRC 20488
#define SMEM_SCAT 24584

__device__ int    g_cls_off[NCLS + 1];
__device__ int    g_cls_src[NCOLS];
__device__ __half g_Ah[(size_t)B_ROWS * FDIM];
__device__ __half g_Whi[NCOLS * FDIM];
__device__ __half g_Wlo[NCOLS * FDIM];
__device__ float  g_scratch[(size_t)B_ROWS * NCOLS];

__device__ __forceinline__ uint32_t smem_u32(const void* p) {
    uint32_t a;
    asm("{ .reg .u64 t; cvta.to.shared.u64 t, %1; cvt.u32.u64 %0, t; }" : "=r"(a) : "l"(p));
    return a;
}
__device__ __forceinline__ void cp16(uint32_t dst, const void* src) {
    asm volatile("cp.async.cg.shared.global [%0], [%1], 16;" :: "r"(dst), "l"(src) : "memory");
}

// ---- prep: deterministic CSR (atomic fill + per-class sort == sequential order) ----
__global__ void prep_kernel(const int* __restrict__ label_ids) {
    __shared__ int lab[NCOLS];
    __shared__ int cnt[NCLS];
    __shared__ int off[NCLS + 1];
    __shared__ int pos[NCLS];
    __shared__ int srcs[NCOLS];
    int t = threadIdx.x;
    lab[t] = label_ids[t];
    if (t < NCLS) cnt[t] = 0;
    __syncthreads();
    atomicAdd(&cnt[lab[t]], 1);
    __syncthreads();
    if (t == 0) {
        int a = 0;
        for (int c = 0; c < NCLS; c++) { off[c] = a; a += cnt[c]; }
        off[NCLS] = a;
    }
    __syncthreads();
    if (t < NCLS) pos[t] = off[t];
    __syncthreads();
    int p = atomicAdd(&pos[lab[t]], 1);
    srcs[p] = t;
    __syncthreads();
    if (t < NCLS) {
        int s0 = off[t], s1 = off[t + 1];
        for (int i = s0 + 1; i < s1; i++) {
            int v = srcs[i], j = i - 1;
            while (j >= s0 && srcs[j] > v) { srcs[j + 1] = srcs[j]; j--; }
            srcs[j + 1] = v;
        }
    }
    __syncthreads();
    if (t <= NCLS) g_cls_off[t] = off[t];
    g_cls_src[t] = srcs[t];
}

// ---- prep: W fp32 -> fp16 hi + lo (exact W = hi + lo to fp16 residual precision) ----
__global__ void prep_split_w(const float* __restrict__ W,
                             __half* __restrict__ Whi, __half* __restrict__ Wlo) {
    size_t i0 = ((size_t)blockIdx.x * 256 + threadIdx.x) * 4;
    float4 v = *(const float4*)(W + i0);
    __half h[4], l[4];
    float x;
    x = v.x; h[0] = __float2half_rn(x); l[0] = __float2half_rn(x - __half2float(h[0]));
    x = v.y; h[1] = __float2half_rn(x); l[1] = __float2half_rn(x - __half2float(h[1]));
    x = v.z; h[2] = __float2half_rn(x); l[2] = __float2half_rn(x - __half2float(h[2]));
    x = v.w; h[3] = __float2half_rn(x); l[3] = __float2half_rn(x - __half2float(h[3]));
    *(uint2*)(Whi + i0) = *(uint2*)h;
    *(uint2*)(Wlo + i0) = *(uint2*)l;
}

// ---- prep: A fp32 -> single fp16 (per row chunk, pipelined) ----
__global__ void prep_a16(const float* __restrict__ A, __half* __restrict__ Ah, int rbase) {
    size_t i0 = (size_t)rbase * FDIM + ((size_t)blockIdx.x * 256 + threadIdx.x) * 4;
    float4 v = *(const float4*)(A + i0);
    __half h[4];
    h[0] = __float2half_rn(v.x);
    h[1] = __float2half_rn(v.y);
    h[2] = __float2half_rn(v.z);
    h[3] = __float2half_rn(v.w);
    *(uint2*)(Ah + i0) = *(uint2*)h;
}

// ---- GEMM: 128x128, fp16 2-product (Ah*Whi + Ah*Wlo == Ah*W), double-buffered ----
__global__ void __launch_bounds__(256, 2)
mhc_gemm(const float* __restrict__ gprob, const float* __restrict__ bias, int rbase) {
    extern __shared__ char smem[];
    const uint32_t sb = smem_u32(smem);
    const int t   = threadIdx.x;
    const int wid = t >> 5;
    const int n0   = blockIdx.x * BN;
    const int row0 = rbase + blockIdx.y * BM;
    const int wm0 = (wid & 3) * 32;
    const int wn0 = (wid >> 2) * 64;

    wmma::fragment<wmma::accumulator, 16, 16, 16, float> acc[2][4];
#pragma unroll
    for (int fm = 0; fm < 2; fm++)
#pragma unroll
        for (int fn = 0; fn < 4; fn++) wmma::fill_fragment(acc[fm][fn], 0.0f);

    auto issue = [&](int it, int s) {
        if (it < NIT) {
            const char* ah = (const char*)(g_Ah  + (size_t)row0 * FDIM + it * BK);
            const char* wh = (const char*)(g_Whi + (size_t)n0 * FDIM + it * BK);
            const char* wl = (const char*)(g_Wlo + (size_t)n0 * FDIM + it * BK);
            uint32_t st = sb + s * STAGE_BYTES;
#pragma unroll
            for (int i = 0; i < 2; i++) {
                int id = i * 256 + t;
                int r = id >> 2, co = (id & 3) * 16;
                size_t go = (size_t)r * 1024 + co;
                uint32_t so = r * 80 + co;
                cp16(st + so,              ah + go);
                cp16(st + TILE_B + so,     wh + go);
                cp16(st + 2 * TILE_B + so, wl + go);
            }
        }
        asm volatile("cp.async.commit_group;" ::: "memory");
    };

    issue(0, 0);
    for (int it = 0; it < NIT; ++it) {
        int s = it & 1;
        issue(it + 1, s ^ 1);
        asm volatile("cp.async.wait_group 1;" ::: "memory");
        __syncthreads();

        const __half* ah_sm = (const __half*)(smem + s * STAGE_BYTES);
        const __half* wh_sm = (const __half*)(smem + s * STAGE_BYTES + TILE_B);
        const __half* wl_sm = (const __half*)(smem + s * STAGE_BYTES + 2 * TILE_B);
#pragma unroll
        for (int kk = 0; kk < BK; kk += 16) {
            wmma::fragment<wmma::matrix_a, 16, 16, 16, __half, wmma::row_major> afh[2];
            wmma::fragment<wmma::matrix_b, 16, 16, 16, __half, wmma::col_major> bfh[4], bfl[4];
#pragma unroll
            for (int fm = 0; fm < 2; fm++)
                wmma::load_matrix_sync(afh[fm], ah_sm + (wm0 + fm * 16) * LDA + kk, LDA);
#pragma unroll
            for (int fn = 0; fn < 4; fn++)
                wmma::load_matrix_sync(bfh[fn], wh_sm + (wn0 + fn * 16) * LDA + kk, LDA);
#pragma unroll
            for (int fm = 0; fm < 2; fm++)
#pragma unroll
                for (int fn = 0; fn < 4; fn++)
                    wmma::mma_sync(acc[fm][fn], afh[fm], bfh[fn], acc[fm][fn]);
#pragma unroll
            for (int fn = 0; fn < 4; fn++)
                wmma::load_matrix_sync(bfl[fn], wl_sm + (wn0 + fn * 16) * LDA + kk, LDA);
#pragma unroll
            for (int fm = 0; fm < 2; fm++)
#pragma unroll
                for (int fn = 0; fn < 4; fn++)
                    wmma::mma_sync(acc[fm][fn], afh[fm], bfl[fn], acc[fm][fn]);
        }
        __syncthreads();
    }

    // ---- epilogue: frags -> smem -> (bias+gprob) -> scratch (coalesced f4) ----
    float* epi = (float*)smem;
#pragma unroll
    for (int fm = 0; fm < 2; fm++)
#pragma unroll
        for (int fn = 0; fn < 4; fn++)
            wmma::store_matrix_sync(epi + (wm0 + fm * 16) * LDE + wn0 + fn * 16,
                                    acc[fm][fn], LDE, wmma::mem_row_major);
    __syncthreads();

#pragma unroll
    for (int i = 0; i < 16; i++) {
        int idx = i * 256 + t;
        int r  = idx >> 5;
        int c4 = (idx & 31) * 4;
        float4 v = *(float4*)(epi + r * LDE + c4);
        int n = n0 + c4;
        float gp = __ldg(gprob + (size_t)(row0 + r) * 16 + (n >> 6));
        v.x = (v.x + __ldg(bias + n + 0)) * gp;
        v.y = (v.y + __ldg(bias + n + 1)) * gp;
        v.z = (v.z + __ldg(bias + n + 2)) * gp;
        v.w = (v.w + __ldg(bias + n + 3)) * gp;
        *(float4*)(g_scratch + (size_t)(row0 + r) * NCOLS + n) = v;
    }
}

// ---- scatter: 4-row tiles, 6 CTAs/SM, class-outer/row-inner gather ----
__global__ void __launch_bounds__(256, 6)
mhc_scatter(float* __restrict__ out, int rbase) {
    extern __shared__ char smem[];
    float* wsm    = (float*)(smem + SC_WSM);
    int*   off_sm = (int*)(smem + SC_OFF);
    int*   src_sm = (int*)(smem + SC_SRC);
    const int t = threadIdx.x;
    const int r0 = rbase + blockIdx.x * SROWS;

    for (int i = t; i <= NCLS; i += 256) off_sm[i] = g_cls_off[i];
    for (int i = t; i < NCOLS; i += 256) src_sm[i] = g_cls_src[i];

    const float4* src = (const float4*)(g_scratch + (size_t)r0 * NCOLS);
    float4* dst4 = (float4*)wsm;
#pragma unroll
    for (int i = 0; i < SROWS * NCOLS / 4 / 256; i++)
        dst4[i * 256 + t] = src[i * 256 + t];
    __syncthreads();

    for (int c = t; c < NCLS; c += 256) {
        int s0 = off_sm[c], s1 = off_sm[c + 1];
        float* ocol = out + (size_t)r0 * NCLS + c;
        if (s1 == s0) {
#pragma unroll
            for (int r = 0; r < SROWS; r++) ocol[(size_t)r * NCLS] = 0.f;
        } else if (s1 == s0 + 1) {
            int src0 = src_sm[s0];
#pragma unroll
            for (int r = 0; r < SROWS; r++)
                ocol[(size_t)r * NCLS] = wsm[r * NCOLS + src0];
        } else {
#pragma unroll
            for (int r = 0; r < SROWS; r++) {
                float s = 0.f;
                for (int k = s0; k < s1; k++) s += wsm[r * NCOLS + src_sm[k]];
                ocol[(size_t)r * NCLS] = s;
            }
        }
    }
}

extern "C" void kernel_launch(void* const* d_in, const int* in_sizes, int n_in,
                              void* d_out, int out_size) {
    const float* features = (const float*)d_in[0];
    const float* gprob    = (const float*)d_in[1];
    const float* W        = (const float*)d_in[2];
    const float* bias     = (const float*)d_in[3];
    const int*   labels   = (const int*)d_in[4];
    float* out = (float*)d_out;

    static __half *hA, *hW, *lW;
    static cudaStream_t s2, sG;
    static cudaEvent_t evF, evS, evG[NCHUNK], evJ, evJG;
    static bool init = false;
    if (!init) {
        cudaGetSymbolAddress((void**)&hA, g_Ah);
        cudaGetSymbolAddress((void**)&hW, g_Whi);
        cudaGetSymbolAddress((void**)&lW, g_Wlo);
        cudaFuncSetAttribute(mhc_gemm, cudaFuncAttributeMaxDynamicSharedMemorySize, SMEM_GEMM);
        cudaFuncSetAttribute(mhc_scatter, cudaFuncAttributeMaxDynamicSharedMemorySize, SMEM_SCAT);
        cudaStreamCreateWithFlags(&s2, cudaStreamNonBlocking);
        cudaStreamCreateWithFlags(&sG, cudaStreamNonBlocking);
        cudaEventCreateWithFlags(&evF, cudaEventDisableTiming);
        cudaEventCreateWithFlags(&evS, cudaEventDisableTiming);
        for (int c = 0; c < NCHUNK; c++)
            cudaEventCreateWithFlags(&evG[c], cudaEventDisableTiming);
        cudaEventCreateWithFlags(&evJ, cudaEventDisableTiming);
        cudaEventCreateWithFlags(&evJG, cudaEventDisableTiming);
        init = true;
    }

    // fork: side stream runs the (independent) CSR prep
    cudaEventRecord(evF, 0);
    cudaStreamWaitEvent(s2, evF, 0);
    prep_kernel<<<1, 1024, 0, s2>>>(labels);

    // W fp16 hi/lo split up front (small); A fp16 conversions are per-chunk, pipelined
    prep_split_w<<<(NCOLS * FDIM) / 1024, 256>>>(W, hW, lW);
    cudaEventRecord(evS, 0);
    cudaStreamWaitEvent(sG, evS, 0);

    for (int c = 0; c < NCHUNK; c++) {
        cudaStream_t gs = (c & 1) ? sG : 0;
        prep_a16<<<(CROWS * FDIM) / 1024, 256, 0, gs>>>(features, hA, c * CROWS);
        dim3 grid(NCOLS / BN, CROWS / BM);
        mhc_gemm<<<grid, 256, SMEM_GEMM, gs>>>(gprob, bias, c * CROWS);
        cudaEventRecord(evG[c], gs);
        cudaStreamWaitEvent(s2, evG[c], 0);
        mhc_scatter<<<CROWS / SROWS, 256, SMEM_SCAT, s2>>>(out, c * CROWS);
    }

    // join both side streams back into stream 0
    cudaEventRecord(evJ, s2);
    cudaStreamWaitEvent(0, evJ, 0);
    cudaEventRecord(evJG, sG);
    cudaStreamWaitEvent(0, evJG, 0);
}

// round 16
// speedup vs baseline: 2.3812x; 1.3905x over previous
#include <cuda_runtime.h>
#include <cuda_fp16.h>
#include <mma.h>
#include <cstdint>

using namespace nvcuda;

#define B_ROWS 32768
#define FDIM   512
#define NCOLS  1024
#define NCLS   1000

#define BM 128
#define BN 128
#define BK 64
#define LDA 72               // fp16 smem pitch (144B, conflict-free LDSM)
#define LDE 136              // fp32 epilogue pitch
#define NIT 8                // 512/64
#define TILE_B 18432         // one 128x64 fp16 tile @ 144B pitch
#define STAGE_BYTES 36864    // Ah + Wh
#define SMEM_GEMM (2 * STAGE_BYTES)   // 73728 (>= epilogue 128*136*4 = 69632)

#define NCHUNK 8
#define CROWS  (B_ROWS / NCHUNK)

// scatter: 4-row tile -> 6 CTAs/SM (measured best)
#define SROWS 4
#define SC_WSM 0
#define SC_OFF 16384
#define SC_SRC 20488
#define SMEM_SCAT 24584

__device__ int    g_cls_off[NCLS + 1];
__device__ int    g_cls_src[NCOLS];
__device__ __half g_Ah[(size_t)B_ROWS * FDIM];
__device__ __half g_Wh[NCOLS * FDIM];
__device__ float  g_scratch[(size_t)B_ROWS * NCOLS];

__device__ __forceinline__ uint32_t smem_u32(const void* p) {
    uint32_t a;
    asm("{ .reg .u64 t; cvta.to.shared.u64 t, %1; cvt.u32.u64 %0, t; }" : "=r"(a) : "l"(p));
    return a;
}
__device__ __forceinline__ void cp16(uint32_t dst, const void* src) {
    asm volatile("cp.async.cg.shared.global [%0], [%1], 16;" :: "r"(dst), "l"(src) : "memory");
}

// ---- prep: deterministic CSR (atomic fill + per-class sort == sequential order) ----
__global__ void prep_kernel(const int* __restrict__ label_ids) {
    __shared__ int lab[NCOLS];
    __shared__ int cnt[NCLS];
    __shared__ int off[NCLS + 1];
    __shared__ int pos[NCLS];
    __shared__ int srcs[NCOLS];
    int t = threadIdx.x;
    lab[t] = label_ids[t];
    if (t < NCLS) cnt[t] = 0;
    __syncthreads();
    atomicAdd(&cnt[lab[t]], 1);
    __syncthreads();
    if (t == 0) {
        int a = 0;
        for (int c = 0; c < NCLS; c++) { off[c] = a; a += cnt[c]; }
        off[NCLS] = a;
    }
    __syncthreads();
    if (t < NCLS) pos[t] = off[t];
    __syncthreads();
    int p = atomicAdd(&pos[lab[t]], 1);
    srcs[p] = t;
    __syncthreads();
    if (t < NCLS) {
        int s0 = off[t], s1 = off[t + 1];
        for (int i = s0 + 1; i < s1; i++) {
            int v = srcs[i], j = i - 1;
            while (j >= s0 && srcs[j] > v) { srcs[j + 1] = srcs[j]; j--; }
            srcs[j + 1] = v;
        }
    }
    __syncthreads();
    if (t <= NCLS) g_cls_off[t] = off[t];
    g_cls_src[t] = srcs[t];
}

// ---- prep: fp32 -> fp16 (W whole, A per chunk) ----
__global__ void prep_w16(const float* __restrict__ W, __half* __restrict__ Wh) {
    size_t i0 = ((size_t)blockIdx.x * 256 + threadIdx.x) * 4;
    float4 v = *(const float4*)(W + i0);
    __half h[4];
    h[0] = __float2half_rn(v.x);
    h[1] = __float2half_rn(v.y);
    h[2] = __float2half_rn(v.z);
    h[3] = __float2half_rn(v.w);
    *(uint2*)(Wh + i0) = *(uint2*)h;
}

__global__ void prep_a16(const float* __restrict__ A, __half* __restrict__ Ah, int rbase) {
    size_t i0 = (size_t)rbase * FDIM + ((size_t)blockIdx.x * 256 + threadIdx.x) * 4;
    float4 v = *(const float4*)(A + i0);
    __half h[4];
    h[0] = __float2half_rn(v.x);
    h[1] = __float2half_rn(v.y);
    h[2] = __float2half_rn(v.z);
    h[3] = __float2half_rn(v.w);
    *(uint2*)(Ah + i0) = *(uint2*)h;
}

// ---- GEMM: 128x128 fp16 single product, BK=64, double-buffered cp.async ----
__global__ void __launch_bounds__(256, 2)
mhc_gemm(const float* __restrict__ gprob, const float* __restrict__ bias, int rbase) {
    extern __shared__ char smem[];
    const uint32_t sb = smem_u32(smem);
    const int t   = threadIdx.x;
    const int wid = t >> 5;
    const int n0   = blockIdx.x * BN;
    const int row0 = rbase + blockIdx.y * BM;
    const int wm0 = (wid & 3) * 32;
    const int wn0 = (wid >> 2) * 64;

    wmma::fragment<wmma::accumulator, 16, 16, 16, float> acc[2][4];
#pragma unroll
    for (int fm = 0; fm < 2; fm++)
#pragma unroll
        for (int fn = 0; fn < 4; fn++) wmma::fill_fragment(acc[fm][fn], 0.0f);

    // per stage: 2 tiles x 1024 16B-chunks (128 rows x 8 chunks); 4/thread each
    auto issue = [&](int it, int s) {
        if (it < NIT) {
            const char* ah = (const char*)(g_Ah + (size_t)row0 * FDIM + it * BK);
            const char* wh = (const char*)(g_Wh + (size_t)n0 * FDIM + it * BK);
            uint32_t st = sb + s * STAGE_BYTES;
#pragma unroll
            for (int i = 0; i < 4; i++) {
                int id = i * 256 + t;
                int r = id >> 3, co = (id & 7) * 16;
                size_t go = (size_t)r * 1024 + co;
                uint32_t so = r * 144 + co;
                cp16(st + so,          ah + go);
                cp16(st + TILE_B + so, wh + go);
            }
        }
        asm volatile("cp.async.commit_group;" ::: "memory");
    };

    issue(0, 0);
    for (int it = 0; it < NIT; ++it) {
        int s = it & 1;
        issue(it + 1, s ^ 1);
        asm volatile("cp.async.wait_group 1;" ::: "memory");
        __syncthreads();

        const __half* ah_sm = (const __half*)(smem + s * STAGE_BYTES);
        const __half* wh_sm = (const __half*)(smem + s * STAGE_BYTES + TILE_B);
#pragma unroll
        for (int kk = 0; kk < BK; kk += 16) {
            wmma::fragment<wmma::matrix_a, 16, 16, 16, __half, wmma::row_major> afh[2];
            wmma::fragment<wmma::matrix_b, 16, 16, 16, __half, wmma::col_major> bfh[4];
#pragma unroll
            for (int fm = 0; fm < 2; fm++)
                wmma::load_matrix_sync(afh[fm], ah_sm + (wm0 + fm * 16) * LDA + kk, LDA);
#pragma unroll
            for (int fn = 0; fn < 4; fn++)
                wmma::load_matrix_sync(bfh[fn], wh_sm + (wn0 + fn * 16) * LDA + kk, LDA);
#pragma unroll
            for (int fm = 0; fm < 2; fm++)
#pragma unroll
                for (int fn = 0; fn < 4; fn++)
                    wmma::mma_sync(acc[fm][fn], afh[fm], bfh[fn], acc[fm][fn]);
        }
        __syncthreads();
    }

    // ---- epilogue: frags -> smem -> (bias+gprob) -> scratch (coalesced f4) ----
    float* epi = (float*)smem;
#pragma unroll
    for (int fm = 0; fm < 2; fm++)
#pragma unroll
        for (int fn = 0; fn < 4; fn++)
            wmma::store_matrix_sync(epi + (wm0 + fm * 16) * LDE + wn0 + fn * 16,
                                    acc[fm][fn], LDE, wmma::mem_row_major);
    __syncthreads();

#pragma unroll
    for (int i = 0; i < 16; i++) {
        int idx = i * 256 + t;
        int r  = idx >> 5;
        int c4 = (idx & 31) * 4;
        float4 v = *(float4*)(epi + r * LDE + c4);
        int n = n0 + c4;
        float gp = __ldg(gprob + (size_t)(row0 + r) * 16 + (n >> 6));
        v.x = (v.x + __ldg(bias + n + 0)) * gp;
        v.y = (v.y + __ldg(bias + n + 1)) * gp;
        v.z = (v.z + __ldg(bias + n + 2)) * gp;
        v.w = (v.w + __ldg(bias + n + 3)) * gp;
        *(float4*)(g_scratch + (size_t)(row0 + r) * NCOLS + n) = v;
    }
}

// ---- scatter: 4-row tiles, 6 CTAs/SM, class-outer/row-inner gather ----
__global__ void __launch_bounds__(256, 6)
mhc_scatter(float* __restrict__ out, int rbase) {
    extern __shared__ char smem[];
    float* wsm    = (float*)(smem + SC_WSM);
    int*   off_sm = (int*)(smem + SC_OFF);
    int*   src_sm = (int*)(smem + SC_SRC);
    const int t = threadIdx.x;
    const int r0 = rbase + blockIdx.x * SROWS;

    for (int i = t; i <= NCLS; i += 256) off_sm[i] = g_cls_off[i];
    for (int i = t; i < NCOLS; i += 256) src_sm[i] = g_cls_src[i];

    const float4* src = (const float4*)(g_scratch + (size_t)r0 * NCOLS);
    float4* dst4 = (float4*)wsm;
#pragma unroll
    for (int i = 0; i < SROWS * NCOLS / 4 / 256; i++)
        dst4[i * 256 + t] = src[i * 256 + t];
    __syncthreads();

    for (int c = t; c < NCLS; c += 256) {
        int s0 = off_sm[c], s1 = off_sm[c + 1];
        float* ocol = out + (size_t)r0 * NCLS + c;
        if (s1 == s0) {
#pragma unroll
            for (int r = 0; r < SROWS; r++) ocol[(size_t)r * NCLS] = 0.f;
        } else if (s1 == s0 + 1) {
            int src0 = src_sm[s0];
#pragma unroll
            for (int r = 0; r < SROWS; r++)
                ocol[(size_t)r * NCLS] = wsm[r * NCOLS + src0];
        } else {
#pragma unroll
            for (int r = 0; r < SROWS; r++) {
                float s = 0.f;
                for (int k = s0; k < s1; k++) s += wsm[r * NCOLS + src_sm[k]];
                ocol[(size_t)r * NCLS] = s;
            }
        }
    }
}

extern "C" void kernel_launch(void* const* d_in, const int* in_sizes, int n_in,
                              void* d_out, int out_size) {
    const float* features = (const float*)d_in[0];
    const float* gprob    = (const float*)d_in[1];
    const float* W        = (const float*)d_in[2];
    const float* bias     = (const float*)d_in[3];
    const int*   labels   = (const int*)d_in[4];
    float* out = (float*)d_out;

    static __half *hA, *hW;
    static cudaStream_t s2, sG;
    static cudaEvent_t evF, evS, evG[NCHUNK], evJ, evJG;
    static bool init = false;
    if (!init) {
        cudaGetSymbolAddress((void**)&hA, g_Ah);
        cudaGetSymbolAddress((void**)&hW, g_Wh);
        cudaFuncSetAttribute(mhc_gemm, cudaFuncAttributeMaxDynamicSharedMemorySize, SMEM_GEMM);
        cudaFuncSetAttribute(mhc_scatter, cudaFuncAttributeMaxDynamicSharedMemorySize, SMEM_SCAT);
        cudaStreamCreateWithFlags(&s2, cudaStreamNonBlocking);
        cudaStreamCreateWithFlags(&sG, cudaStreamNonBlocking);
        cudaEventCreateWithFlags(&evF, cudaEventDisableTiming);
        cudaEventCreateWithFlags(&evS, cudaEventDisableTiming);
        for (int c = 0; c < NCHUNK; c++)
            cudaEventCreateWithFlags(&evG[c], cudaEventDisableTiming);
        cudaEventCreateWithFlags(&evJ, cudaEventDisableTiming);
        cudaEventCreateWithFlags(&evJG, cudaEventDisableTiming);
        init = true;
    }

    // fork: side stream runs the (independent) CSR prep
    cudaEventRecord(evF, 0);
    cudaStreamWaitEvent(s2, evF, 0);
    prep_kernel<<<1, 1024, 0, s2>>>(labels);

    // W fp16 convert up front (small); A fp16 conversions are per-chunk, pipelined
    prep_w16<<<(NCOLS * FDIM) / 1024, 256>>>(W, hW);
    cudaEventRecord(evS, 0);
    cudaStreamWaitEvent(sG, evS, 0);

    for (int c = 0; c < NCHUNK; c++) {
        cudaStream_t gs = (c & 1) ? sG : 0;
        prep_a16<<<(CROWS * FDIM) / 1024, 256, 0, gs>>>(features, hA, c * CROWS);
        dim3 grid(NCOLS / BN, CROWS / BM);
        mhc_gemm<<<grid, 256, SMEM_GEMM, gs>>>(gprob, bias, c * CROWS);
        cudaEventRecord(evG[c], gs);
        cudaStreamWaitEvent(s2, evG[c], 0);
        mhc_scatter<<<CROWS / SROWS, 256, SMEM_SCAT, s2>>>(out, c * CROWS);
    }

    // join both side streams back into stream 0
    cudaEventRecord(evJ, s2);
    cudaStreamWaitEvent(0, evJ, 0);
    cudaEventRecord(evJG, sG);
    cudaStreamWaitEvent(0, evJG, 0);
}